// round 1
// baseline (speedup 1.0000x reference)
#include <cuda_runtime.h>
#include <math.h>

#define B_ 4
#define L_ 4096
#define D_ 1024
#define H_ 16
#define W_ 64
#define HD_ 64
#define ML_ (B_*L_)      // 16384 rows total
#define EPS_ 1e-5f
#define PAD 68           // smem row stride for 64-wide tiles (16B aligned, conflict-avoiding)

// Scratch (allocation-free rule: __device__ globals)
__device__ float g_qkv [(size_t)ML_ * 3 * D_];   // 192 MB: [B*L, 3*D]
__device__ float g_attn[(size_t)ML_ * D_];       //  64 MB: [B*L, D]
__device__ float g_y   [(size_t)ML_ * D_];       //  64 MB: pre-LN residual sum

// ---------------------------------------------------------------------------
// C[M,N] = A[M,K] @ Bw[N,K]^T + bias[N] (+ R[M,N] if RESID)
// 128x128 block tile, K-tile 8, 256 threads, 8x8 per-thread microtile.
// ---------------------------------------------------------------------------
template<int RESID>
__global__ void __launch_bounds__(256) sgemm_tn(const float* __restrict__ A,
                                                const float* __restrict__ Bw,
                                                const float* __restrict__ bias,
                                                const float* __restrict__ R,
                                                float* __restrict__ C,
                                                int M, int N, int K)
{
    __shared__ float As[8][128];
    __shared__ float Bs[8][128];
    const int tid = threadIdx.x;
    const int tx = tid & 15, ty = tid >> 4;
    const int bm = blockIdx.y << 7, bn = blockIdx.x << 7;
    const int lr = tid >> 1;          // 0..127
    const int lk = (tid & 1) << 2;    // 0 or 4
    const float* Ap = A  + (size_t)(bm + lr) * K + lk;
    const float* Bp = Bw + (size_t)(bn + lr) * K + lk;

    float acc[8][8];
#pragma unroll
    for (int i = 0; i < 8; i++)
#pragma unroll
        for (int j = 0; j < 8; j++) acc[i][j] = 0.f;

    for (int k0 = 0; k0 < K; k0 += 8) {
        float4 av = *(const float4*)(Ap + k0);
        float4 bv = *(const float4*)(Bp + k0);
        __syncthreads();
        As[lk+0][lr] = av.x; As[lk+1][lr] = av.y; As[lk+2][lr] = av.z; As[lk+3][lr] = av.w;
        Bs[lk+0][lr] = bv.x; Bs[lk+1][lr] = bv.y; Bs[lk+2][lr] = bv.z; Bs[lk+3][lr] = bv.w;
        __syncthreads();
#pragma unroll
        for (int kk = 0; kk < 8; kk++) {
            float4 a0 = *(const float4*)&As[kk][ty << 3];
            float4 a1 = *(const float4*)&As[kk][(ty << 3) + 4];
            float4 b0 = *(const float4*)&Bs[kk][tx << 3];
            float4 b1 = *(const float4*)&Bs[kk][(tx << 3) + 4];
            float a[8] = {a0.x, a0.y, a0.z, a0.w, a1.x, a1.y, a1.z, a1.w};
            float b[8] = {b0.x, b0.y, b0.z, b0.w, b1.x, b1.y, b1.z, b1.w};
#pragma unroll
            for (int i = 0; i < 8; i++)
#pragma unroll
                for (int j = 0; j < 8; j++)
                    acc[i][j] = fmaf(a[i], b[j], acc[i][j]);
        }
    }

#pragma unroll
    for (int i = 0; i < 8; i++) {
        const int row = bm + (ty << 3) + i;
        const int col = bn + (tx << 3);
        float* Cp = C + (size_t)row * N + col;
        const float* Rp = RESID ? (R + (size_t)row * N + col) : (const float*)0;
#pragma unroll
        for (int j = 0; j < 8; j += 4) {
            float4 bb = *(const float4*)(bias + col + j);
            float4 v;
            v.x = acc[i][j]   + bb.x;
            v.y = acc[i][j+1] + bb.y;
            v.z = acc[i][j+2] + bb.z;
            v.w = acc[i][j+3] + bb.w;
            if (RESID) {
                float4 rv = *(const float4*)(Rp + j);
                v.x += rv.x; v.y += rv.y; v.z += rv.z; v.w += rv.w;
            }
            *(float4*)(Cp + j) = v;
        }
    }
}

// ---------------------------------------------------------------------------
// Windowed attention: one block per (window, head, batch). 64x64x64 tile.
// qkv layout: [B*L, 3*D], q at col h*64, k at 1024+h*64, v at 2048+h*64.
// ---------------------------------------------------------------------------
__global__ void __launch_bounds__(256) attn_kernel(const float* __restrict__ qkv,
                                                   float* __restrict__ out)
{
    extern __shared__ float sm[];
    float* Qs = sm;                 // 64 x PAD (reused as P after softmax)
    float* Ks = sm +     64 * PAD;
    float* Vs = sm + 2 * 64 * PAD;
    const int tid = threadIdx.x;
    const size_t base = ((size_t)(blockIdx.z * L_ + blockIdx.x * W_)) * (3 * D_)
                        + blockIdx.y * HD_;

    // cooperative load of Q,K,V (64x64 fp32 each) with float4
    for (int i = tid; i < 64 * 16; i += 256) {
        const int r = i >> 4, c = (i & 15) << 2;
        const float* p = qkv + base + (size_t)r * (3 * D_) + c;
        *(float4*)(Qs + r * PAD + c) = *(const float4*)(p);
        *(float4*)(Ks + r * PAD + c) = *(const float4*)(p + D_);
        *(float4*)(Vs + r * PAD + c) = *(const float4*)(p + 2 * D_);
    }
    __syncthreads();

    const int r  = tid >> 2;        // query row 0..63
    const int c0 = (tid & 3) << 4;  // 16-col chunk

    // S = Q K^T * scale (per-thread 16 scores)
    float s[16];
#pragma unroll
    for (int i = 0; i < 16; i++) s[i] = 0.f;
    for (int k = 0; k < 64; k += 4) {
        float4 qv = *(const float4*)(Qs + r * PAD + k);
#pragma unroll
        for (int ci = 0; ci < 16; ci++) {
            float4 kv = *(const float4*)(Ks + (c0 + ci) * PAD + k);
            s[ci] += qv.x * kv.x + qv.y * kv.y + qv.z * kv.z + qv.w * kv.w;
        }
    }

    // softmax across 64 cols: 4 threads/row, shuffle-reduce within group of 4
    float mx = -3.0e38f;
#pragma unroll
    for (int i = 0; i < 16; i++) { s[i] *= 0.125f; mx = fmaxf(mx, s[i]); }
    mx = fmaxf(mx, __shfl_xor_sync(0xffffffffu, mx, 1));
    mx = fmaxf(mx, __shfl_xor_sync(0xffffffffu, mx, 2));
    float sum = 0.f;
#pragma unroll
    for (int i = 0; i < 16; i++) { s[i] = __expf(s[i] - mx); sum += s[i]; }
    sum += __shfl_xor_sync(0xffffffffu, sum, 1);
    sum += __shfl_xor_sync(0xffffffffu, sum, 2);
    const float inv = 1.0f / sum;

    __syncthreads();                 // all Q reads done before overwrite with P
#pragma unroll
    for (int i = 0; i < 16; i++) Qs[r * PAD + c0 + i] = s[i] * inv;
    __syncthreads();

    // O = P V  (per-thread 16 output features)
    float o[16];
#pragma unroll
    for (int i = 0; i < 16; i++) o[i] = 0.f;
    for (int k = 0; k < 64; k++) {
        const float p = Qs[r * PAD + k];
#pragma unroll
        for (int j = 0; j < 16; j += 4) {
            float4 vv = *(const float4*)(Vs + k * PAD + c0 + j);
            o[j]   = fmaf(p, vv.x, o[j]);
            o[j+1] = fmaf(p, vv.y, o[j+1]);
            o[j+2] = fmaf(p, vv.z, o[j+2]);
            o[j+3] = fmaf(p, vv.w, o[j+3]);
        }
    }

    float* op = out + ((size_t)(blockIdx.z * L_ + blockIdx.x * W_ + r)) * D_
                    + blockIdx.y * HD_ + c0;
#pragma unroll
    for (int j = 0; j < 16; j += 4)
        *(float4*)(op + j) = make_float4(o[j], o[j+1], o[j+2], o[j+3]);
}

// ---------------------------------------------------------------------------
// LayerNorm: one block per row of 1024, 256 threads x float4.
// ---------------------------------------------------------------------------
__global__ void __launch_bounds__(256) ln_kernel(const float* __restrict__ y,
                                                 const float* __restrict__ gamma,
                                                 const float* __restrict__ beta,
                                                 float* __restrict__ out)
{
    __shared__ float red[8];
    const int row = blockIdx.x, tid = threadIdx.x;
    const float* yr = y + (size_t)row * D_;
    float4 v = *(const float4*)(yr + (tid << 2));

    float sAcc = v.x + v.y + v.z + v.w;
#pragma unroll
    for (int o = 16; o > 0; o >>= 1) sAcc += __shfl_xor_sync(0xffffffffu, sAcc, o);
    if ((tid & 31) == 0) red[tid >> 5] = sAcc;
    __syncthreads();
    float tot = 0.f;
#pragma unroll
    for (int i = 0; i < 8; i++) tot += red[i];
    const float mean = tot * (1.0f / 1024.0f);

    const float dx = v.x - mean, dy = v.y - mean, dz = v.z - mean, dw = v.w - mean;
    float s2 = dx * dx + dy * dy + dz * dz + dw * dw;
#pragma unroll
    for (int o = 16; o > 0; o >>= 1) s2 += __shfl_xor_sync(0xffffffffu, s2, o);
    __syncthreads();
    if ((tid & 31) == 0) red[tid >> 5] = s2;
    __syncthreads();
    float tot2 = 0.f;
#pragma unroll
    for (int i = 0; i < 8; i++) tot2 += red[i];
    const float rstd = rsqrtf(tot2 * (1.0f / 1024.0f) + EPS_);

    float4 g  = *(const float4*)(gamma + (tid << 2));
    float4 be = *(const float4*)(beta  + (tid << 2));
    float4 o4 = make_float4(dx * rstd * g.x + be.x,
                            dy * rstd * g.y + be.y,
                            dz * rstd * g.z + be.z,
                            dw * rstd * g.w + be.w);
    *(float4*)(out + (size_t)row * D_ + (tid << 2)) = o4;
}

// ---------------------------------------------------------------------------
extern "C" void kernel_launch(void* const* d_in, const int* in_sizes, int n_in,
                              void* d_out, int out_size)
{
    const float* x     = (const float*)d_in[0];
    const float* Wqkv  = (const float*)d_in[1];
    const float* bqkv  = (const float*)d_in[2];
    const float* Wproj = (const float*)d_in[3];
    const float* bproj = (const float*)d_in[4];
    const float* gamma = (const float*)d_in[5];
    const float* beta  = (const float*)d_in[6];
    float* out = (float*)d_out;

    float *qkv, *attn, *y;
    cudaGetSymbolAddress((void**)&qkv,  g_qkv);
    cudaGetSymbolAddress((void**)&attn, g_attn);
    cudaGetSymbolAddress((void**)&y,    g_y);

    const int attn_smem = 3 * 64 * PAD * (int)sizeof(float);  // 52224 B
    cudaFuncSetAttribute(attn_kernel, cudaFuncAttributeMaxDynamicSharedMemorySize,
                         attn_smem);

    // 1) QKV projection: [16384,1024] @ [1024,3072]^T(row-major NxK) + bias
    sgemm_tn<0><<<dim3(24, 128), 256>>>(x, Wqkv, bqkv, (const float*)0, qkv,
                                        ML_, 3 * D_, D_);
    // 2) windowed attention: 4096 independent 64x64x64 tiles
    attn_kernel<<<dim3(64, 16, 4), 256, attn_smem>>>(qkv, attn);
    // 3) output projection + bias + residual
    sgemm_tn<1><<<dim3(8, 128), 256>>>(attn, Wproj, bproj, x, y,
                                       ML_, D_, D_);
    // 4) layernorm
    ln_kernel<<<ML_, 256>>>(y, gamma, beta, out);
}

// round 4
// speedup vs baseline: 2.2778x; 2.2778x over previous
#include <cuda_runtime.h>
#include <cstdint>

#define B_ 4
#define L_ 4096
#define D_ 1024
#define H_ 16
#define W_ 64
#define HD_ 64
#define ML_ (B_*L_)      // 16384 rows
#define EPS_ 1e-5f
#define PAD 68

// Scratch (allocation-free rule: __device__ globals)
__device__ float g_qkv [(size_t)ML_ * 3 * D_];   // [B*L, 3*D]
__device__ float g_attn[(size_t)ML_ * D_];       // [B*L, D]
__device__ float g_y   [(size_t)ML_ * D_];       // pre-LN residual sum

// ---------------------------------------------------------------------------
// mma.sync tf32 helpers (base PTX ISA — works on compute_103 virtual arch)
// ---------------------------------------------------------------------------
__device__ __forceinline__ uint32_t f2tf32(float f) {
    uint32_t u;
    asm("cvt.rna.tf32.f32 %0, %1;" : "=r"(u) : "f"(f));
    return u;
}

__device__ __forceinline__ void mma_16x8x8_tf32(float* c, const uint32_t* a,
                                                const uint32_t* b) {
    asm volatile(
        "mma.sync.aligned.m16n8k8.row.col.f32.tf32.tf32.f32 "
        "{%0,%1,%2,%3}, {%4,%5,%6,%7}, {%8,%9}, {%0,%1,%2,%3};"
        : "+f"(c[0]), "+f"(c[1]), "+f"(c[2]), "+f"(c[3])
        : "r"(a[0]), "r"(a[1]), "r"(a[2]), "r"(a[3]), "r"(b[0]), "r"(b[1]));
}

// ---------------------------------------------------------------------------
// Tensor-core GEMM via mma.sync: C[M,N] = A[M,K] @ Bw[N,K]^T + bias (+R)
// CTA 128x128, K-tile 32, 2-stage SMEM, warp tile 64x32 (4x4 m16n8k8).
// SMEM row stride 36 words -> conflict-free fragment LDS and float4 STS.
// ---------------------------------------------------------------------------
#define TS 36                    // smem row stride (words)
#define BUFW (128*TS*2)          // words per stage (A then B)
#define GEMM_SMEM (2*BUFW*4)     // 73728 B

template<int RESID>
__global__ void __launch_bounds__(256, 1) gemm_mma(
    const float* __restrict__ A, const float* __restrict__ Bw,
    const float* __restrict__ bias, const float* __restrict__ R,
    float* __restrict__ C, int M, int N, int K)
{
    extern __shared__ float sm[];
    const int tid  = threadIdx.x;
    const int wid  = tid >> 5, lane = tid & 31;
    const int g    = lane >> 2, tg = lane & 3;      // mma groupID / thread-in-group
    const int wm   = (wid >> 2) << 6;               // warp m offset: 0 or 64
    const int wn   = (wid & 3) << 5;                // warp n offset: 0/32/64/96
    const int bm   = blockIdx.y << 7, bn = blockIdx.x << 7;
    const int r0   = tid >> 3, c0 = (tid & 7) << 2; // global-load coords
    const int ntk  = K >> 5;                        // K-tiles of 32

    float acc[4][4][4];
#pragma unroll
    for (int mi = 0; mi < 4; mi++)
#pragma unroll
        for (int ni = 0; ni < 4; ni++)
#pragma unroll
            for (int i = 0; i < 4; i++) acc[mi][ni][i] = 0.f;

    float4 pa[4], pb[4];

    auto ldg_tile = [&](int kt) {
        const int kc = kt << 5;
#pragma unroll
        for (int i = 0; i < 4; i++) {
            pa[i] = *(const float4*)(A  + (size_t)(bm + r0 + (i << 5)) * K + kc + c0);
            pb[i] = *(const float4*)(Bw + (size_t)(bn + r0 + (i << 5)) * K + kc + c0);
        }
    };
    auto sts_tile = [&](int buf) {
        float* As = sm + buf * BUFW;
        float* Bs = As + 128 * TS;
#pragma unroll
        for (int i = 0; i < 4; i++) {
            const int off = (r0 + (i << 5)) * TS + c0;
            uint4 ua = make_uint4(f2tf32(pa[i].x), f2tf32(pa[i].y),
                                  f2tf32(pa[i].z), f2tf32(pa[i].w));
            uint4 ub = make_uint4(f2tf32(pb[i].x), f2tf32(pb[i].y),
                                  f2tf32(pb[i].z), f2tf32(pb[i].w));
            *(uint4*)(As + off) = ua;
            *(uint4*)(Bs + off) = ub;
        }
    };

    ldg_tile(0);
    sts_tile(0);
    __syncthreads();

    for (int kt = 0; kt < ntk; kt++) {
        const int cur = kt & 1;
        if (kt + 1 < ntk) ldg_tile(kt + 1);

        const uint32_t* As = (const uint32_t*)(sm + cur * BUFW);
        const uint32_t* Bs = As + 128 * TS;
#pragma unroll
        for (int ks = 0; ks < 4; ks++) {
            const int ko = ks << 3;
            uint32_t af[4][4], bf[4][2];
#pragma unroll
            for (int mi = 0; mi < 4; mi++) {
                const int row = wm + (mi << 4) + g;
                af[mi][0] = As[row * TS + ko + tg];
                af[mi][1] = As[(row + 8) * TS + ko + tg];
                af[mi][2] = As[row * TS + ko + tg + 4];
                af[mi][3] = As[(row + 8) * TS + ko + tg + 4];
            }
#pragma unroll
            for (int ni = 0; ni < 4; ni++) {
                const int nr = wn + (ni << 3) + g;
                bf[ni][0] = Bs[nr * TS + ko + tg];
                bf[ni][1] = Bs[nr * TS + ko + tg + 4];
            }
#pragma unroll
            for (int mi = 0; mi < 4; mi++)
#pragma unroll
                for (int ni = 0; ni < 4; ni++)
                    mma_16x8x8_tf32(acc[mi][ni], af[mi], bf[ni]);
        }

        if (kt + 1 < ntk) sts_tile(cur ^ 1);
        __syncthreads();
    }

    // Epilogue: c0,c1 are (row, 2tg/2tg+1); c2,c3 same cols at row+8
#pragma unroll
    for (int mi = 0; mi < 4; mi++) {
#pragma unroll
        for (int ni = 0; ni < 4; ni++) {
            const int row = bm + wm + (mi << 4) + g;
            const int col = bn + wn + (ni << 3) + (tg << 1);
            float2 bb = *(const float2*)(bias + col);
            float2 v0 = make_float2(acc[mi][ni][0] + bb.x, acc[mi][ni][1] + bb.y);
            float2 v1 = make_float2(acc[mi][ni][2] + bb.x, acc[mi][ni][3] + bb.y);
            if (RESID) {
                float2 ra = *(const float2*)(R + (size_t)row * N + col);
                float2 rb = *(const float2*)(R + (size_t)(row + 8) * N + col);
                v0.x += ra.x; v0.y += ra.y; v1.x += rb.x; v1.y += rb.y;
            }
            *(float2*)(C + (size_t)row * N + col)       = v0;
            *(float2*)(C + (size_t)(row + 8) * N + col) = v1;
        }
    }
}

// ---------------------------------------------------------------------------
// Windowed attention (fp32 SIMT): one block per (window, head, batch).
// ---------------------------------------------------------------------------
__global__ void __launch_bounds__(256) attn_kernel(const float* __restrict__ qkv,
                                                   float* __restrict__ out)
{
    extern __shared__ float smf[];
    float* Qs = smf;
    float* Ks = smf +     64 * PAD;
    float* Vs = smf + 2 * 64 * PAD;
    const int tid = threadIdx.x;
    const size_t base = ((size_t)(blockIdx.z * L_ + blockIdx.x * W_)) * (3 * D_)
                        + blockIdx.y * HD_;

    for (int i = tid; i < 64 * 16; i += 256) {
        const int r = i >> 4, c = (i & 15) << 2;
        const float* p = qkv + base + (size_t)r * (3 * D_) + c;
        *(float4*)(Qs + r * PAD + c) = *(const float4*)(p);
        *(float4*)(Ks + r * PAD + c) = *(const float4*)(p + D_);
        *(float4*)(Vs + r * PAD + c) = *(const float4*)(p + 2 * D_);
    }
    __syncthreads();

    const int r  = tid >> 2;
    const int c0 = (tid & 3) << 4;

    float s[16];
#pragma unroll
    for (int i = 0; i < 16; i++) s[i] = 0.f;
    for (int k = 0; k < 64; k += 4) {
        float4 qv = *(const float4*)(Qs + r * PAD + k);
#pragma unroll
        for (int ci = 0; ci < 16; ci++) {
            float4 kv = *(const float4*)(Ks + (c0 + ci) * PAD + k);
            s[ci] += qv.x * kv.x + qv.y * kv.y + qv.z * kv.z + qv.w * kv.w;
        }
    }

    float mx = -3.0e38f;
#pragma unroll
    for (int i = 0; i < 16; i++) { s[i] *= 0.125f; mx = fmaxf(mx, s[i]); }
    mx = fmaxf(mx, __shfl_xor_sync(0xffffffffu, mx, 1));
    mx = fmaxf(mx, __shfl_xor_sync(0xffffffffu, mx, 2));
    float sum = 0.f;
#pragma unroll
    for (int i = 0; i < 16; i++) { s[i] = __expf(s[i] - mx); sum += s[i]; }
    sum += __shfl_xor_sync(0xffffffffu, sum, 1);
    sum += __shfl_xor_sync(0xffffffffu, sum, 2);
    const float inv = 1.0f / sum;

    __syncthreads();
#pragma unroll
    for (int i = 0; i < 16; i++) Qs[r * PAD + c0 + i] = s[i] * inv;
    __syncthreads();

    float o[16];
#pragma unroll
    for (int i = 0; i < 16; i++) o[i] = 0.f;
    for (int k = 0; k < 64; k++) {
        const float p = Qs[r * PAD + k];
#pragma unroll
        for (int j = 0; j < 16; j += 4) {
            float4 vv = *(const float4*)(Vs + k * PAD + c0 + j);
            o[j]   = fmaf(p, vv.x, o[j]);
            o[j+1] = fmaf(p, vv.y, o[j+1]);
            o[j+2] = fmaf(p, vv.z, o[j+2]);
            o[j+3] = fmaf(p, vv.w, o[j+3]);
        }
    }

    float* op = out + ((size_t)(blockIdx.z * L_ + blockIdx.x * W_ + r)) * D_
                    + blockIdx.y * HD_ + c0;
#pragma unroll
    for (int j = 0; j < 16; j += 4)
        *(float4*)(op + j) = make_float4(o[j], o[j+1], o[j+2], o[j+3]);
}

// ---------------------------------------------------------------------------
// LayerNorm: one block per row of 1024.
// ---------------------------------------------------------------------------
__global__ void __launch_bounds__(256) ln_kernel(const float* __restrict__ y,
                                                 const float* __restrict__ gamma,
                                                 const float* __restrict__ beta,
                                                 float* __restrict__ out)
{
    __shared__ float red[8];
    const int row = blockIdx.x, tid = threadIdx.x;
    const float* yr = y + (size_t)row * D_;
    float4 v = *(const float4*)(yr + (tid << 2));

    float sAcc = v.x + v.y + v.z + v.w;
#pragma unroll
    for (int o = 16; o > 0; o >>= 1) sAcc += __shfl_xor_sync(0xffffffffu, sAcc, o);
    if ((tid & 31) == 0) red[tid >> 5] = sAcc;
    __syncthreads();
    float tot = 0.f;
#pragma unroll
    for (int i = 0; i < 8; i++) tot += red[i];
    const float mean = tot * (1.0f / 1024.0f);

    const float dx = v.x - mean, dy = v.y - mean, dz = v.z - mean, dw = v.w - mean;
    float s2 = dx * dx + dy * dy + dz * dz + dw * dw;
#pragma unroll
    for (int o = 16; o > 0; o >>= 1) s2 += __shfl_xor_sync(0xffffffffu, s2, o);
    __syncthreads();
    if ((tid & 31) == 0) red[tid >> 5] = s2;
    __syncthreads();
    float tot2 = 0.f;
#pragma unroll
    for (int i = 0; i < 8; i++) tot2 += red[i];
    const float rstd = rsqrtf(tot2 * (1.0f / 1024.0f) + EPS_);

    float4 gm = *(const float4*)(gamma + (tid << 2));
    float4 be = *(const float4*)(beta  + (tid << 2));
    float4 o4 = make_float4(dx * rstd * gm.x + be.x,
                            dy * rstd * gm.y + be.y,
                            dz * rstd * gm.z + be.z,
                            dw * rstd * gm.w + be.w);
    *(float4*)(out + (size_t)row * D_ + (tid << 2)) = o4;
}

// ---------------------------------------------------------------------------
extern "C" void kernel_launch(void* const* d_in, const int* in_sizes, int n_in,
                              void* d_out, int out_size)
{
    const float* x     = (const float*)d_in[0];
    const float* Wqkv  = (const float*)d_in[1];
    const float* bqkv  = (const float*)d_in[2];
    const float* Wproj = (const float*)d_in[3];
    const float* bproj = (const float*)d_in[4];
    const float* gamma = (const float*)d_in[5];
    const float* beta  = (const float*)d_in[6];
    float* out = (float*)d_out;

    float *qkv, *attn, *y;
    cudaGetSymbolAddress((void**)&qkv,  g_qkv);
    cudaGetSymbolAddress((void**)&attn, g_attn);
    cudaGetSymbolAddress((void**)&y,    g_y);

    cudaFuncSetAttribute(gemm_mma<0>, cudaFuncAttributeMaxDynamicSharedMemorySize, GEMM_SMEM);
    cudaFuncSetAttribute(gemm_mma<1>, cudaFuncAttributeMaxDynamicSharedMemorySize, GEMM_SMEM);
    const int attn_smem = 3 * 64 * PAD * (int)sizeof(float);
    cudaFuncSetAttribute(attn_kernel, cudaFuncAttributeMaxDynamicSharedMemorySize, attn_smem);

    // 1) QKV projection (tf32 mma.sync tensor cores)
    gemm_mma<0><<<dim3(24, 128), 256, GEMM_SMEM>>>(x, Wqkv, bqkv, x, qkv,
                                                   ML_, 3 * D_, D_);
    // 2) windowed attention
    attn_kernel<<<dim3(64, 16, 4), 256, attn_smem>>>(qkv, attn);
    // 3) output projection + bias + residual (tf32 mma.sync)
    gemm_mma<1><<<dim3(8, 128), 256, GEMM_SMEM>>>(attn, Wproj, bproj, x, y,
                                                  ML_, D_, D_);
    // 4) layernorm
    ln_kernel<<<ML_, 256>>>(y, gamma, beta, out);
}

// round 5
// speedup vs baseline: 3.5382x; 1.5533x over previous
#include <cuda_runtime.h>
#include <cstdint>

#define B_ 4
#define L_ 4096
#define D_ 1024
#define H_ 16
#define W_ 64
#define HD_ 64
#define ML_ (B_*L_)      // 16384 rows
#define EPS_ 1e-5f

// Scratch (allocation-free rule: __device__ globals)
__device__ float g_qkv [(size_t)ML_ * 3 * D_];   // [B*L, 3*D] (tf32-rounded)
__device__ float g_attn[(size_t)ML_ * D_];       // [B*L, D]   (tf32-rounded)
__device__ float g_y   [(size_t)ML_ * D_];       // pre-LN residual sum
__device__ float g_xr  [(size_t)ML_ * D_];       // x rounded to tf32
__device__ float g_wq  [(size_t)3 * D_ * D_];    // Wqkv rounded
__device__ float g_wp  [(size_t)D_ * D_];        // Wproj rounded

// ---------------------------------------------------------------------------
__device__ __forceinline__ uint32_t f2tf32(float f) {
    uint32_t u;
    asm("cvt.rna.tf32.f32 %0, %1;" : "=r"(u) : "f"(f));
    return u;
}
__device__ __forceinline__ float rtf32(float f) {
    return __uint_as_float(f2tf32(f));
}
__device__ __forceinline__ uint32_t smem_u32(const void* p) {
    uint32_t a;
    asm("{ .reg .u64 t; cvta.to.shared.u64 t, %1; cvt.u32.u64 %0, t; }"
        : "=r"(a) : "l"(p));
    return a;
}
__device__ __forceinline__ void cp16(uint32_t dst, const void* src) {
    asm volatile("cp.async.cg.shared.global [%0], [%1], 16;"
                 :: "r"(dst), "l"(src) : "memory");
}
__device__ __forceinline__ void mma_16x8x8_tf32(float* c, const uint32_t* a,
                                                const uint32_t* b) {
    asm volatile(
        "mma.sync.aligned.m16n8k8.row.col.f32.tf32.tf32.f32 "
        "{%0,%1,%2,%3}, {%4,%5,%6,%7}, {%8,%9}, {%0,%1,%2,%3};"
        : "+f"(c[0]), "+f"(c[1]), "+f"(c[2]), "+f"(c[3])
        : "r"(a[0]), "r"(a[1]), "r"(a[2]), "r"(a[3]), "r"(b[0]), "r"(b[1]));
}

// ---------------------------------------------------------------------------
// Elementwise tf32 rounding prepass
// ---------------------------------------------------------------------------
__global__ void round_tf32(const float* __restrict__ in, float* __restrict__ out,
                           int n4)
{
    int i = blockIdx.x * blockDim.x + threadIdx.x;
    if (i < n4) {
        float4 v = ((const float4*)in)[i];
        v.x = rtf32(v.x); v.y = rtf32(v.y); v.z = rtf32(v.z); v.w = rtf32(v.w);
        ((float4*)out)[i] = v;
    }
}

// ---------------------------------------------------------------------------
// Tensor-core GEMM via mma.sync + cp.async: C = A @ Bw^T + bias (+R)
// Operands pre-rounded to tf32. CTA 128x128, K-tile 32, 2-stage cp.async.
// ---------------------------------------------------------------------------
#define TS 36
#define BUFW (128*TS*2)
#define GEMM_SMEM (2*BUFW*4)     // 73728 B

template<int RESID, int ROUND>
__global__ void __launch_bounds__(256) gemm_mma(
    const float* __restrict__ A, const float* __restrict__ Bw,
    const float* __restrict__ bias, const float* __restrict__ R,
    float* __restrict__ C, int M, int N, int K)
{
    extern __shared__ float sm[];
    const uint32_t sbase = smem_u32(sm);
    const int tid  = threadIdx.x;
    const int wid  = tid >> 5, lane = tid & 31;
    const int g    = lane >> 2, tg = lane & 3;
    const int wm   = (wid >> 2) << 6;
    const int wn   = (wid & 3) << 5;
    const int bm   = blockIdx.y << 7, bn = blockIdx.x << 7;
    const int r0   = tid >> 3, c0 = (tid & 7) << 2;
    const int ntk  = K >> 5;

    float acc[4][4][4];
#pragma unroll
    for (int mi = 0; mi < 4; mi++)
#pragma unroll
        for (int ni = 0; ni < 4; ni++)
#pragma unroll
            for (int i = 0; i < 4; i++) acc[mi][ni][i] = 0.f;

    auto cp_tile = [&](int kt, int buf) {
        const int kc = kt << 5;
        const uint32_t da = sbase + (uint32_t)((buf * BUFW + r0 * TS + c0) << 2);
        const uint32_t db = da + (uint32_t)((128 * TS) << 2);
#pragma unroll
        for (int i = 0; i < 4; i++) {
            cp16(da + (uint32_t)((i << 5) * TS << 2),
                 A  + (size_t)(bm + r0 + (i << 5)) * K + kc + c0);
            cp16(db + (uint32_t)((i << 5) * TS << 2),
                 Bw + (size_t)(bn + r0 + (i << 5)) * K + kc + c0);
        }
        asm volatile("cp.async.commit_group;" ::: "memory");
    };

    cp_tile(0, 0);
    cp_tile(1, 1);

    for (int kt = 0; kt < ntk; kt++) {
        if (kt < ntk - 1)
            asm volatile("cp.async.wait_group 1;" ::: "memory");
        else
            asm volatile("cp.async.wait_group 0;" ::: "memory");
        __syncthreads();

        const uint32_t* As = (const uint32_t*)(sm + (kt & 1) * BUFW);
        const uint32_t* Bs = As + 128 * TS;
#pragma unroll
        for (int ks = 0; ks < 4; ks++) {
            const int ko = ks << 3;
            uint32_t af[4][4], bf[4][2];
#pragma unroll
            for (int mi = 0; mi < 4; mi++) {
                const int row = wm + (mi << 4) + g;
                af[mi][0] = As[row * TS + ko + tg];
                af[mi][1] = As[(row + 8) * TS + ko + tg];
                af[mi][2] = As[row * TS + ko + tg + 4];
                af[mi][3] = As[(row + 8) * TS + ko + tg + 4];
            }
#pragma unroll
            for (int ni = 0; ni < 4; ni++) {
                const int nr = wn + (ni << 3) + g;
                bf[ni][0] = Bs[nr * TS + ko + tg];
                bf[ni][1] = Bs[nr * TS + ko + tg + 4];
            }
#pragma unroll
            for (int mi = 0; mi < 4; mi++)
#pragma unroll
                for (int ni = 0; ni < 4; ni++)
                    mma_16x8x8_tf32(acc[mi][ni], af[mi], bf[ni]);
        }
        __syncthreads();
        if (kt + 2 < ntk) cp_tile(kt + 2, kt & 1);
    }

#pragma unroll
    for (int mi = 0; mi < 4; mi++) {
#pragma unroll
        for (int ni = 0; ni < 4; ni++) {
            const int row = bm + wm + (mi << 4) + g;
            const int col = bn + wn + (ni << 3) + (tg << 1);
            float2 bb = *(const float2*)(bias + col);
            float2 v0 = make_float2(acc[mi][ni][0] + bb.x, acc[mi][ni][1] + bb.y);
            float2 v1 = make_float2(acc[mi][ni][2] + bb.x, acc[mi][ni][3] + bb.y);
            if (RESID) {
                float2 ra = *(const float2*)(R + (size_t)row * N + col);
                float2 rb = *(const float2*)(R + (size_t)(row + 8) * N + col);
                v0.x += ra.x; v0.y += ra.y; v1.x += rb.x; v1.y += rb.y;
            }
            if (ROUND) {
                v0.x = rtf32(v0.x); v0.y = rtf32(v0.y);
                v1.x = rtf32(v1.x); v1.y = rtf32(v1.y);
            }
            *(float2*)(C + (size_t)row * N + col)       = v0;
            *(float2*)(C + (size_t)(row + 8) * N + col) = v1;
        }
    }
}

// ---------------------------------------------------------------------------
// Windowed attention on tensor cores. 1 block = 1 (window, head, batch).
// 4 warps; warp w owns rows [16w, 16w+16). QKV pre-rounded to tf32.
// ---------------------------------------------------------------------------
#define APAD 68
#define ATTN_SMEM (3*64*APAD*4)

__global__ void __launch_bounds__(128) attn_mma(const float* __restrict__ qkv,
                                                float* __restrict__ out)
{
    extern __shared__ float smf[];
    float* Qs = smf;                 // 64 x 68 (rows reused for P per-warp)
    float* Ks = smf +     64 * APAD;
    float* Vs = smf + 2 * 64 * APAD;
    const int tid  = threadIdx.x;
    const int wid  = tid >> 5, lane = tid & 31;
    const int g    = lane >> 2, tg = lane & 3;
    const int m0   = wid << 4;
    const size_t base = ((size_t)(blockIdx.z * L_ + blockIdx.x * W_)) * (3 * D_)
                        + blockIdx.y * HD_;

    for (int i = tid; i < 64 * 16; i += 128) {
        const int r = i >> 4, c = (i & 15) << 2;
        const float* p = qkv + base + (size_t)r * (3 * D_) + c;
        *(float4*)(Qs + r * APAD + c) = *(const float4*)(p);
        *(float4*)(Ks + r * APAD + c) = *(const float4*)(p + D_);
        *(float4*)(Vs + r * APAD + c) = *(const float4*)(p + 2 * D_);
    }
    __syncthreads();

    // S = Q K^T: 8 n-tiles of 8 cols, K (contraction=hd) in 8 steps of 8
    float s[8][4];
#pragma unroll
    for (int t = 0; t < 8; t++)
#pragma unroll
        for (int i = 0; i < 4; i++) s[t][i] = 0.f;

#pragma unroll
    for (int ks = 0; ks < 8; ks++) {
        const int ko = ks << 3;
        uint32_t a[4];
        a[0] = __float_as_uint(Qs[(m0 + g) * APAD + ko + tg]);
        a[1] = __float_as_uint(Qs[(m0 + g + 8) * APAD + ko + tg]);
        a[2] = __float_as_uint(Qs[(m0 + g) * APAD + ko + tg + 4]);
        a[3] = __float_as_uint(Qs[(m0 + g + 8) * APAD + ko + tg + 4]);
#pragma unroll
        for (int t = 0; t < 8; t++) {
            uint32_t b[2];
            b[0] = __float_as_uint(Ks[((t << 3) + g) * APAD + ko + tg]);
            b[1] = __float_as_uint(Ks[((t << 3) + g) * APAD + ko + tg + 4]);
            mma_16x8x8_tf32(s[t], a, b);
        }
    }

    // softmax over 64 cols; rows g (c0,c1) and g+8 (c2,c3), quad-shuffle reduce
    float mxl = -3.0e38f, mxh = -3.0e38f;
#pragma unroll
    for (int t = 0; t < 8; t++) {
#pragma unroll
        for (int i = 0; i < 4; i++) s[t][i] *= 0.125f;
        mxl = fmaxf(mxl, fmaxf(s[t][0], s[t][1]));
        mxh = fmaxf(mxh, fmaxf(s[t][2], s[t][3]));
    }
    mxl = fmaxf(mxl, __shfl_xor_sync(0xffffffffu, mxl, 1));
    mxl = fmaxf(mxl, __shfl_xor_sync(0xffffffffu, mxl, 2));
    mxh = fmaxf(mxh, __shfl_xor_sync(0xffffffffu, mxh, 1));
    mxh = fmaxf(mxh, __shfl_xor_sync(0xffffffffu, mxh, 2));

    float sl = 0.f, sh = 0.f;
#pragma unroll
    for (int t = 0; t < 8; t++) {
        s[t][0] = __expf(s[t][0] - mxl); sl += s[t][0];
        s[t][1] = __expf(s[t][1] - mxl); sl += s[t][1];
        s[t][2] = __expf(s[t][2] - mxh); sh += s[t][2];
        s[t][3] = __expf(s[t][3] - mxh); sh += s[t][3];
    }
    sl += __shfl_xor_sync(0xffffffffu, sl, 1);
    sl += __shfl_xor_sync(0xffffffffu, sl, 2);
    sh += __shfl_xor_sync(0xffffffffu, sh, 1);
    sh += __shfl_xor_sync(0xffffffffu, sh, 2);
    const float il = 1.0f / sl, ih = 1.0f / sh;

    // write P (tf32-rounded) into this warp's private Q rows
#pragma unroll
    for (int t = 0; t < 8; t++) {
        const int cc = (t << 3) + (tg << 1);
        *(float2*)(Qs + (m0 + g) * APAD + cc) =
            make_float2(rtf32(s[t][0] * il), rtf32(s[t][1] * il));
        *(float2*)(Qs + (m0 + g + 8) * APAD + cc) =
            make_float2(rtf32(s[t][2] * ih), rtf32(s[t][3] * ih));
    }
    __syncwarp();

    // O = P V : contraction over keys (8 steps), V read as col-major B
    float o[8][4];
#pragma unroll
    for (int t = 0; t < 8; t++)
#pragma unroll
        for (int i = 0; i < 4; i++) o[t][i] = 0.f;

#pragma unroll
    for (int ks = 0; ks < 8; ks++) {
        const int ko = ks << 3;
        uint32_t a[4];
        a[0] = __float_as_uint(Qs[(m0 + g) * APAD + ko + tg]);
        a[1] = __float_as_uint(Qs[(m0 + g + 8) * APAD + ko + tg]);
        a[2] = __float_as_uint(Qs[(m0 + g) * APAD + ko + tg + 4]);
        a[3] = __float_as_uint(Qs[(m0 + g + 8) * APAD + ko + tg + 4]);
#pragma unroll
        for (int t = 0; t < 8; t++) {
            uint32_t b[2];
            b[0] = __float_as_uint(Vs[(ko + tg) * APAD + (t << 3) + g]);
            b[1] = __float_as_uint(Vs[(ko + tg + 4) * APAD + (t << 3) + g]);
            mma_16x8x8_tf32(o[t], a, b);
        }
    }

    // store O (tf32-rounded: it feeds the proj GEMM)
    const size_t row = (size_t)(blockIdx.z * L_ + blockIdx.x * W_ + m0 + g);
    const int colb = blockIdx.y * HD_;
#pragma unroll
    for (int t = 0; t < 8; t++) {
        const int cc = colb + (t << 3) + (tg << 1);
        *(float2*)(out + row * D_ + cc) =
            make_float2(rtf32(o[t][0]), rtf32(o[t][1]));
        *(float2*)(out + (row + 8) * D_ + cc) =
            make_float2(rtf32(o[t][2]), rtf32(o[t][3]));
    }
}

// ---------------------------------------------------------------------------
// LayerNorm: one block per row of 1024.
// ---------------------------------------------------------------------------
__global__ void __launch_bounds__(256) ln_kernel(const float* __restrict__ y,
                                                 const float* __restrict__ gamma,
                                                 const float* __restrict__ beta,
                                                 float* __restrict__ out)
{
    __shared__ float red[8];
    const int row = blockIdx.x, tid = threadIdx.x;
    const float* yr = y + (size_t)row * D_;
    float4 v = *(const float4*)(yr + (tid << 2));

    float sAcc = v.x + v.y + v.z + v.w;
#pragma unroll
    for (int o = 16; o > 0; o >>= 1) sAcc += __shfl_xor_sync(0xffffffffu, sAcc, o);
    if ((tid & 31) == 0) red[tid >> 5] = sAcc;
    __syncthreads();
    float tot = 0.f;
#pragma unroll
    for (int i = 0; i < 8; i++) tot += red[i];
    const float mean = tot * (1.0f / 1024.0f);

    const float dx = v.x - mean, dy = v.y - mean, dz = v.z - mean, dw = v.w - mean;
    float s2 = dx * dx + dy * dy + dz * dz + dw * dw;
#pragma unroll
    for (int o = 16; o > 0; o >>= 1) s2 += __shfl_xor_sync(0xffffffffu, s2, o);
    __syncthreads();
    if ((tid & 31) == 0) red[tid >> 5] = s2;
    __syncthreads();
    float tot2 = 0.f;
#pragma unroll
    for (int i = 0; i < 8; i++) tot2 += red[i];
    const float rstd = rsqrtf(tot2 * (1.0f / 1024.0f) + EPS_);

    float4 gm = *(const float4*)(gamma + (tid << 2));
    float4 be = *(const float4*)(beta  + (tid << 2));
    float4 o4 = make_float4(dx * rstd * gm.x + be.x,
                            dy * rstd * gm.y + be.y,
                            dz * rstd * gm.z + be.z,
                            dw * rstd * gm.w + be.w);
    *(float4*)(out + (size_t)row * D_ + (tid << 2)) = o4;
}

// ---------------------------------------------------------------------------
extern "C" void kernel_launch(void* const* d_in, const int* in_sizes, int n_in,
                              void* d_out, int out_size)
{
    const float* x     = (const float*)d_in[0];
    const float* Wqkv  = (const float*)d_in[1];
    const float* bqkv  = (const float*)d_in[2];
    const float* Wproj = (const float*)d_in[3];
    const float* bproj = (const float*)d_in[4];
    const float* gamma = (const float*)d_in[5];
    const float* beta  = (const float*)d_in[6];
    float* out = (float*)d_out;

    float *qkv, *attn, *y, *xr, *wq, *wp;
    cudaGetSymbolAddress((void**)&qkv,  g_qkv);
    cudaGetSymbolAddress((void**)&attn, g_attn);
    cudaGetSymbolAddress((void**)&y,    g_y);
    cudaGetSymbolAddress((void**)&xr,   g_xr);
    cudaGetSymbolAddress((void**)&wq,   g_wq);
    cudaGetSymbolAddress((void**)&wp,   g_wp);

    cudaFuncSetAttribute(gemm_mma<0,1>, cudaFuncAttributeMaxDynamicSharedMemorySize, GEMM_SMEM);
    cudaFuncSetAttribute(gemm_mma<1,0>, cudaFuncAttributeMaxDynamicSharedMemorySize, GEMM_SMEM);
    cudaFuncSetAttribute(attn_mma, cudaFuncAttributeMaxDynamicSharedMemorySize, ATTN_SMEM);

    // 0) round GEMM operands to tf32 once
    round_tf32<<<(ML_*D_/4 + 255)/256, 256>>>(x,     xr, ML_*D_/4);
    round_tf32<<<(3*D_*D_/4 + 255)/256, 256>>>(Wqkv, wq, 3*D_*D_/4);
    round_tf32<<<(D_*D_/4 + 255)/256, 256>>>(Wproj,  wp, D_*D_/4);

    // 1) QKV projection (epilogue rounds Q,K,V for the attention MMA)
    gemm_mma<0,1><<<dim3(24, 128), 256, GEMM_SMEM>>>(xr, wq, bqkv, xr, qkv,
                                                     ML_, 3 * D_, D_);
    // 2) windowed attention on tensor cores
    attn_mma<<<dim3(64, 16, 4), 128, ATTN_SMEM>>>(qkv, attn);
    // 3) output projection + bias + residual (residual = original x)
    gemm_mma<1,0><<<dim3(8, 128), 256, GEMM_SMEM>>>(attn, wp, bproj, x, y,
                                                    ML_, D_, D_);
    // 4) layernorm
    ln_kernel<<<ML_, 256>>>(y, gamma, beta, out);
}

// round 6
// speedup vs baseline: 4.0914x; 1.1564x over previous
#include <cuda_runtime.h>
#include <cstdint>

#define B_ 4
#define L_ 4096
#define D_ 1024
#define H_ 16
#define W_ 64
#define HD_ 64
#define ML_ (B_*L_)      // 16384 rows
#define EPS_ 1e-5f

// Scratch (allocation-free rule: __device__ globals)
__device__ float g_qkv [(size_t)ML_ * 3 * D_];   // [B*L, 3*D] (tf32-rounded)
__device__ float g_attn[(size_t)ML_ * D_];       // [B*L, D]   (tf32-rounded)
__device__ float g_y   [(size_t)ML_ * D_];       // pre-LN residual sum
__device__ float g_xr  [(size_t)ML_ * D_];       // x rounded to tf32
__device__ float g_wq  [(size_t)3 * D_ * D_];    // Wqkv rounded
__device__ float g_wp  [(size_t)D_ * D_];        // Wproj rounded

// ---------------------------------------------------------------------------
__device__ __forceinline__ uint32_t f2tf32(float f) {
    uint32_t u;
    asm("cvt.rna.tf32.f32 %0, %1;" : "=r"(u) : "f"(f));
    return u;
}
__device__ __forceinline__ float rtf32(float f) {
    return __uint_as_float(f2tf32(f));
}
__device__ __forceinline__ uint32_t smem_u32(const void* p) {
    uint32_t a;
    asm("{ .reg .u64 t; cvta.to.shared.u64 t, %1; cvt.u32.u64 %0, t; }"
        : "=r"(a) : "l"(p));
    return a;
}
__device__ __forceinline__ void cp16(uint32_t dst, const void* src) {
    asm volatile("cp.async.cg.shared.global [%0], [%1], 16;"
                 :: "r"(dst), "l"(src) : "memory");
}
__device__ __forceinline__ void mma_16x8x8_tf32(float* c, const uint32_t* a,
                                                const uint32_t* b) {
    asm volatile(
        "mma.sync.aligned.m16n8k8.row.col.f32.tf32.tf32.f32 "
        "{%0,%1,%2,%3}, {%4,%5,%6,%7}, {%8,%9}, {%0,%1,%2,%3};"
        : "+f"(c[0]), "+f"(c[1]), "+f"(c[2]), "+f"(c[3])
        : "r"(a[0]), "r"(a[1]), "r"(a[2]), "r"(a[3]), "r"(b[0]), "r"(b[1]));
}

// ---------------------------------------------------------------------------
// Elementwise tf32 rounding prepass
// ---------------------------------------------------------------------------
__global__ void round_tf32(const float* __restrict__ in, float* __restrict__ out,
                           int n4)
{
    int i = blockIdx.x * blockDim.x + threadIdx.x;
    if (i < n4) {
        float4 v = ((const float4*)in)[i];
        v.x = rtf32(v.x); v.y = rtf32(v.y); v.z = rtf32(v.z); v.w = rtf32(v.w);
        ((float4*)out)[i] = v;
    }
}

// ---------------------------------------------------------------------------
// Tensor-core GEMM via mma.sync + cp.async: C = A @ Bw^T + bias (+R)
// Operands pre-rounded to tf32. CTA 128x128, K-tile 32, 3-stage cp.async,
// one __syncthreads per K-tile, 2 CTAs/SM (__launch_bounds__(256,2)).
// ---------------------------------------------------------------------------
#define TS 36
#define BUFW (128*TS*2)          // words per stage (A then B)
#define GEMM_SMEM (3*BUFW*4)     // 110592 B

template<int RESID, int ROUND>
__global__ void __launch_bounds__(256, 2) gemm_mma(
    const float* __restrict__ A, const float* __restrict__ Bw,
    const float* __restrict__ bias, const float* __restrict__ R,
    float* __restrict__ C, int M, int N, int K)
{
    extern __shared__ float sm[];
    const uint32_t sbase = smem_u32(sm);
    const int tid  = threadIdx.x;
    const int wid  = tid >> 5, lane = tid & 31;
    const int g    = lane >> 2, tg = lane & 3;
    const int wm   = (wid >> 2) << 6;
    const int wn   = (wid & 3) << 5;
    const int bm   = blockIdx.y << 7, bn = blockIdx.x << 7;
    const int r0   = tid >> 3, c0 = (tid & 7) << 2;
    const int ntk  = K >> 5;

    float acc[4][4][4];
#pragma unroll
    for (int mi = 0; mi < 4; mi++)
#pragma unroll
        for (int ni = 0; ni < 4; ni++)
#pragma unroll
            for (int i = 0; i < 4; i++) acc[mi][ni][i] = 0.f;

    auto cp_tile = [&](int kt, int buf) {
        const int kc = kt << 5;
        const uint32_t da = sbase + (uint32_t)((buf * BUFW + r0 * TS + c0) << 2);
        const uint32_t db = da + (uint32_t)((128 * TS) << 2);
#pragma unroll
        for (int i = 0; i < 4; i++) {
            cp16(da + (uint32_t)((i << 5) * TS << 2),
                 A  + (size_t)(bm + r0 + (i << 5)) * K + kc + c0);
            cp16(db + (uint32_t)((i << 5) * TS << 2),
                 Bw + (size_t)(bn + r0 + (i << 5)) * K + kc + c0);
        }
        asm volatile("cp.async.commit_group;" ::: "memory");
    };

    cp_tile(0, 0);
    if (ntk > 1) cp_tile(1, 1);

    int buf = 0;
    for (int kt = 0; kt < ntk; kt++) {
        if (kt < ntk - 1)
            asm volatile("cp.async.wait_group 1;" ::: "memory");
        else
            asm volatile("cp.async.wait_group 0;" ::: "memory");
        __syncthreads();

        // issue next stage into the buffer last read at kt-1 (safe post-sync)
        if (kt + 2 < ntk) {
            int nb = buf + 2; if (nb >= 3) nb -= 3;
            cp_tile(kt + 2, nb);
        }

        const uint32_t* As = (const uint32_t*)(sm + buf * BUFW);
        const uint32_t* Bs = As + 128 * TS;
#pragma unroll
        for (int ks = 0; ks < 4; ks++) {
            const int ko = ks << 3;
            uint32_t af[4][4], bf[4][2];
#pragma unroll
            for (int mi = 0; mi < 4; mi++) {
                const int row = wm + (mi << 4) + g;
                af[mi][0] = As[row * TS + ko + tg];
                af[mi][1] = As[(row + 8) * TS + ko + tg];
                af[mi][2] = As[row * TS + ko + tg + 4];
                af[mi][3] = As[(row + 8) * TS + ko + tg + 4];
            }
#pragma unroll
            for (int ni = 0; ni < 4; ni++) {
                const int nr = wn + (ni << 3) + g;
                bf[ni][0] = Bs[nr * TS + ko + tg];
                bf[ni][1] = Bs[nr * TS + ko + tg + 4];
            }
#pragma unroll
            for (int mi = 0; mi < 4; mi++)
#pragma unroll
                for (int ni = 0; ni < 4; ni++)
                    mma_16x8x8_tf32(acc[mi][ni], af[mi], bf[ni]);
        }
        if (++buf == 3) buf = 0;
    }

#pragma unroll
    for (int mi = 0; mi < 4; mi++) {
#pragma unroll
        for (int ni = 0; ni < 4; ni++) {
            const int row = bm + wm + (mi << 4) + g;
            const int col = bn + wn + (ni << 3) + (tg << 1);
            float2 bb = *(const float2*)(bias + col);
            float2 v0 = make_float2(acc[mi][ni][0] + bb.x, acc[mi][ni][1] + bb.y);
            float2 v1 = make_float2(acc[mi][ni][2] + bb.x, acc[mi][ni][3] + bb.y);
            if (RESID) {
                float2 ra = *(const float2*)(R + (size_t)row * N + col);
                float2 rb = *(const float2*)(R + (size_t)(row + 8) * N + col);
                v0.x += ra.x; v0.y += ra.y; v1.x += rb.x; v1.y += rb.y;
            }
            if (ROUND) {
                v0.x = rtf32(v0.x); v0.y = rtf32(v0.y);
                v1.x = rtf32(v1.x); v1.y = rtf32(v1.y);
            }
            *(float2*)(C + (size_t)row * N + col)       = v0;
            *(float2*)(C + (size_t)(row + 8) * N + col) = v1;
        }
    }
}

// ---------------------------------------------------------------------------
// Windowed attention on tensor cores. 1 block = 1 (window, head, batch).
// 4 warps; warp w owns rows [16w, 16w+16). QKV pre-rounded to tf32.
// ---------------------------------------------------------------------------
#define APAD 68
#define ATTN_SMEM (3*64*APAD*4)

__global__ void __launch_bounds__(128) attn_mma(const float* __restrict__ qkv,
                                                float* __restrict__ out)
{
    extern __shared__ float smf[];
    float* Qs = smf;                 // 64 x 68 (rows reused for P per-warp)
    float* Ks = smf +     64 * APAD;
    float* Vs = smf + 2 * 64 * APAD;
    const int tid  = threadIdx.x;
    const int wid  = tid >> 5, lane = tid & 31;
    const int g    = lane >> 2, tg = lane & 3;
    const int m0   = wid << 4;
    const size_t base = ((size_t)(blockIdx.z * L_ + blockIdx.x * W_)) * (3 * D_)
                        + blockIdx.y * HD_;

    for (int i = tid; i < 64 * 16; i += 128) {
        const int r = i >> 4, c = (i & 15) << 2;
        const float* p = qkv + base + (size_t)r * (3 * D_) + c;
        *(float4*)(Qs + r * APAD + c) = *(const float4*)(p);
        *(float4*)(Ks + r * APAD + c) = *(const float4*)(p + D_);
        *(float4*)(Vs + r * APAD + c) = *(const float4*)(p + 2 * D_);
    }
    __syncthreads();

    // S = Q K^T
    float s[8][4];
#pragma unroll
    for (int t = 0; t < 8; t++)
#pragma unroll
        for (int i = 0; i < 4; i++) s[t][i] = 0.f;

#pragma unroll
    for (int ks = 0; ks < 8; ks++) {
        const int ko = ks << 3;
        uint32_t a[4];
        a[0] = __float_as_uint(Qs[(m0 + g) * APAD + ko + tg]);
        a[1] = __float_as_uint(Qs[(m0 + g + 8) * APAD + ko + tg]);
        a[2] = __float_as_uint(Qs[(m0 + g) * APAD + ko + tg + 4]);
        a[3] = __float_as_uint(Qs[(m0 + g + 8) * APAD + ko + tg + 4]);
#pragma unroll
        for (int t = 0; t < 8; t++) {
            uint32_t b[2];
            b[0] = __float_as_uint(Ks[((t << 3) + g) * APAD + ko + tg]);
            b[1] = __float_as_uint(Ks[((t << 3) + g) * APAD + ko + tg + 4]);
            mma_16x8x8_tf32(s[t], a, b);
        }
    }

    // softmax over 64 cols; rows g (c0,c1) and g+8 (c2,c3)
    float mxl = -3.0e38f, mxh = -3.0e38f;
#pragma unroll
    for (int t = 0; t < 8; t++) {
#pragma unroll
        for (int i = 0; i < 4; i++) s[t][i] *= 0.125f;
        mxl = fmaxf(mxl, fmaxf(s[t][0], s[t][1]));
        mxh = fmaxf(mxh, fmaxf(s[t][2], s[t][3]));
    }
    mxl = fmaxf(mxl, __shfl_xor_sync(0xffffffffu, mxl, 1));
    mxl = fmaxf(mxl, __shfl_xor_sync(0xffffffffu, mxl, 2));
    mxh = fmaxf(mxh, __shfl_xor_sync(0xffffffffu, mxh, 1));
    mxh = fmaxf(mxh, __shfl_xor_sync(0xffffffffu, mxh, 2));

    float sl = 0.f, sh = 0.f;
#pragma unroll
    for (int t = 0; t < 8; t++) {
        s[t][0] = __expf(s[t][0] - mxl); sl += s[t][0];
        s[t][1] = __expf(s[t][1] - mxl); sl += s[t][1];
        s[t][2] = __expf(s[t][2] - mxh); sh += s[t][2];
        s[t][3] = __expf(s[t][3] - mxh); sh += s[t][3];
    }
    sl += __shfl_xor_sync(0xffffffffu, sl, 1);
    sl += __shfl_xor_sync(0xffffffffu, sl, 2);
    sh += __shfl_xor_sync(0xffffffffu, sh, 1);
    sh += __shfl_xor_sync(0xffffffffu, sh, 2);
    const float il = 1.0f / sl, ih = 1.0f / sh;

#pragma unroll
    for (int t = 0; t < 8; t++) {
        const int cc = (t << 3) + (tg << 1);
        *(float2*)(Qs + (m0 + g) * APAD + cc) =
            make_float2(rtf32(s[t][0] * il), rtf32(s[t][1] * il));
        *(float2*)(Qs + (m0 + g + 8) * APAD + cc) =
            make_float2(rtf32(s[t][2] * ih), rtf32(s[t][3] * ih));
    }
    __syncwarp();

    // O = P V
    float o[8][4];
#pragma unroll
    for (int t = 0; t < 8; t++)
#pragma unroll
        for (int i = 0; i < 4; i++) o[t][i] = 0.f;

#pragma unroll
    for (int ks = 0; ks < 8; ks++) {
        const int ko = ks << 3;
        uint32_t a[4];
        a[0] = __float_as_uint(Qs[(m0 + g) * APAD + ko + tg]);
        a[1] = __float_as_uint(Qs[(m0 + g + 8) * APAD + ko + tg]);
        a[2] = __float_as_uint(Qs[(m0 + g) * APAD + ko + tg + 4]);
        a[3] = __float_as_uint(Qs[(m0 + g + 8) * APAD + ko + tg + 4]);
#pragma unroll
        for (int t = 0; t < 8; t++) {
            uint32_t b[2];
            b[0] = __float_as_uint(Vs[(ko + tg) * APAD + (t << 3) + g]);
            b[1] = __float_as_uint(Vs[(ko + tg + 4) * APAD + (t << 3) + g]);
            mma_16x8x8_tf32(o[t], a, b);
        }
    }

    const size_t row = (size_t)(blockIdx.z * L_ + blockIdx.x * W_ + m0 + g);
    const int colb = blockIdx.y * HD_;
#pragma unroll
    for (int t = 0; t < 8; t++) {
        const int cc = colb + (t << 3) + (tg << 1);
        *(float2*)(out + row * D_ + cc) =
            make_float2(rtf32(o[t][0]), rtf32(o[t][1]));
        *(float2*)(out + (row + 8) * D_ + cc) =
            make_float2(rtf32(o[t][2]), rtf32(o[t][3]));
    }
}

// ---------------------------------------------------------------------------
// LayerNorm: one block per row of 1024.
// ---------------------------------------------------------------------------
__global__ void __launch_bounds__(256) ln_kernel(const float* __restrict__ y,
                                                 const float* __restrict__ gamma,
                                                 const float* __restrict__ beta,
                                                 float* __restrict__ out)
{
    __shared__ float red[8];
    const int row = blockIdx.x, tid = threadIdx.x;
    const float* yr = y + (size_t)row * D_;
    float4 v = *(const float4*)(yr + (tid << 2));

    float sAcc = v.x + v.y + v.z + v.w;
#pragma unroll
    for (int o = 16; o > 0; o >>= 1) sAcc += __shfl_xor_sync(0xffffffffu, sAcc, o);
    if ((tid & 31) == 0) red[tid >> 5] = sAcc;
    __syncthreads();
    float tot = 0.f;
#pragma unroll
    for (int i = 0; i < 8; i++) tot += red[i];
    const float mean = tot * (1.0f / 1024.0f);

    const float dx = v.x - mean, dy = v.y - mean, dz = v.z - mean, dw = v.w - mean;
    float s2 = dx * dx + dy * dy + dz * dz + dw * dw;
#pragma unroll
    for (int o = 16; o > 0; o >>= 1) s2 += __shfl_xor_sync(0xffffffffu, s2, o);
    __syncthreads();
    if ((tid & 31) == 0) red[tid >> 5] = s2;
    __syncthreads();
    float tot2 = 0.f;
#pragma unroll
    for (int i = 0; i < 8; i++) tot2 += red[i];
    const float rstd = rsqrtf(tot2 * (1.0f / 1024.0f) + EPS_);

    float4 gm = *(const float4*)(gamma + (tid << 2));
    float4 be = *(const float4*)(beta  + (tid << 2));
    float4 o4 = make_float4(dx * rstd * gm.x + be.x,
                            dy * rstd * gm.y + be.y,
                            dz * rstd * gm.z + be.z,
                            dw * rstd * gm.w + be.w);
    *(float4*)(out + (size_t)row * D_ + (tid << 2)) = o4;
}

// ---------------------------------------------------------------------------
extern "C" void kernel_launch(void* const* d_in, const int* in_sizes, int n_in,
                              void* d_out, int out_size)
{
    const float* x     = (const float*)d_in[0];
    const float* Wqkv  = (const float*)d_in[1];
    const float* bqkv  = (const float*)d_in[2];
    const float* Wproj = (const float*)d_in[3];
    const float* bproj = (const float*)d_in[4];
    const float* gamma = (const float*)d_in[5];
    const float* beta  = (const float*)d_in[6];
    float* out = (float*)d_out;

    float *qkv, *attn, *y, *xr, *wq, *wp;
    cudaGetSymbolAddress((void**)&qkv,  g_qkv);
    cudaGetSymbolAddress((void**)&attn, g_attn);
    cudaGetSymbolAddress((void**)&y,    g_y);
    cudaGetSymbolAddress((void**)&xr,   g_xr);
    cudaGetSymbolAddress((void**)&wq,   g_wq);
    cudaGetSymbolAddress((void**)&wp,   g_wp);

    cudaFuncSetAttribute(gemm_mma<0,1>, cudaFuncAttributeMaxDynamicSharedMemorySize, GEMM_SMEM);
    cudaFuncSetAttribute(gemm_mma<1,0>, cudaFuncAttributeMaxDynamicSharedMemorySize, GEMM_SMEM);
    cudaFuncSetAttribute(attn_mma, cudaFuncAttributeMaxDynamicSharedMemorySize, ATTN_SMEM);

    // 0) round GEMM operands to tf32 once
    round_tf32<<<(ML_*D_/4 + 255)/256, 256>>>(x,     xr, ML_*D_/4);
    round_tf32<<<(3*D_*D_/4 + 255)/256, 256>>>(Wqkv, wq, 3*D_*D_/4);
    round_tf32<<<(D_*D_/4 + 255)/256, 256>>>(Wproj,  wp, D_*D_/4);

    // 1) QKV projection (epilogue rounds Q,K,V for the attention MMA)
    gemm_mma<0,1><<<dim3(24, 128), 256, GEMM_SMEM>>>(xr, wq, bqkv, xr, qkv,
                                                     ML_, 3 * D_, D_);
    // 2) windowed attention on tensor cores
    attn_mma<<<dim3(64, 16, 4), 128, ATTN_SMEM>>>(qkv, attn);
    // 3) output projection + bias + residual (residual = original x)
    gemm_mma<1,0><<<dim3(8, 128), 256, GEMM_SMEM>>>(attn, wp, bproj, x, y,
                                                    ML_, D_, D_);
    // 4) layernorm
    ln_kernel<<<ML_, 256>>>(y, gamma, beta, out);
}

// round 7
// speedup vs baseline: 4.5020x; 1.1004x over previous
#include <cuda_runtime.h>
#include <cstdint>

#define B_ 4
#define L_ 4096
#define D_ 1024
#define H_ 16
#define W_ 64
#define HD_ 64
#define ML_ (B_*L_)      // 16384 rows
#define EPS_ 1e-5f

// Scratch (allocation-free rule: __device__ globals)
__device__ float g_qkv [(size_t)ML_ * 3 * D_];   // [B*L, 3*D] (tf32-rounded)
__device__ float g_attn[(size_t)ML_ * D_];       // [B*L, D]   (tf32-rounded)
__device__ float g_y   [(size_t)ML_ * D_];       // pre-LN residual sum
__device__ float g_xr  [(size_t)ML_ * D_];       // x rounded to tf32
__device__ float g_wq  [(size_t)3 * D_ * D_];    // Wqkv rounded
__device__ float g_wp  [(size_t)D_ * D_];        // Wproj rounded

// ---------------------------------------------------------------------------
__device__ __forceinline__ uint32_t f2tf32(float f) {
    uint32_t u;
    asm("cvt.rna.tf32.f32 %0, %1;" : "=r"(u) : "f"(f));
    return u;
}
__device__ __forceinline__ float rtf32(float f) {
    return __uint_as_float(f2tf32(f));
}
__device__ __forceinline__ uint32_t smem_u32(const void* p) {
    uint32_t a;
    asm("{ .reg .u64 t; cvta.to.shared.u64 t, %1; cvt.u32.u64 %0, t; }"
        : "=r"(a) : "l"(p));
    return a;
}
__device__ __forceinline__ void cp16(uint32_t dst, const void* src) {
    asm volatile("cp.async.cg.shared.global [%0], [%1], 16;"
                 :: "r"(dst), "l"(src) : "memory");
}
__device__ __forceinline__ void mma_16x8x8_tf32(float* c, const uint32_t* a,
                                                const uint32_t* b) {
    asm volatile(
        "mma.sync.aligned.m16n8k8.row.col.f32.tf32.tf32.f32 "
        "{%0,%1,%2,%3}, {%4,%5,%6,%7}, {%8,%9}, {%0,%1,%2,%3};"
        : "+f"(c[0]), "+f"(c[1]), "+f"(c[2]), "+f"(c[3])
        : "r"(a[0]), "r"(a[1]), "r"(a[2]), "r"(a[3]), "r"(b[0]), "r"(b[1]));
}
// ldmatrix x4 b16: viewed as b32, r_i[lane l] = tile_i[l>>2][l&3] where
// tile_i is addressed by lanes 8i..8i+7 (lane j -> row j of the 8x(16B) tile).
__device__ __forceinline__ void ldsm4(uint32_t* r, uint32_t addr) {
    asm volatile("ldmatrix.sync.aligned.m8n8.x4.shared.b16 {%0,%1,%2,%3}, [%4];"
                 : "=r"(r[0]), "=r"(r[1]), "=r"(r[2]), "=r"(r[3]) : "r"(addr));
}

// ---------------------------------------------------------------------------
// Elementwise tf32 rounding prepass
// ---------------------------------------------------------------------------
__global__ void round_tf32(const float* __restrict__ in, float* __restrict__ out,
                           int n4)
{
    int i = blockIdx.x * blockDim.x + threadIdx.x;
    if (i < n4) {
        float4 v = ((const float4*)in)[i];
        v.x = rtf32(v.x); v.y = rtf32(v.y); v.z = rtf32(v.z); v.w = rtf32(v.w);
        ((float4*)out)[i] = v;
    }
}

// ---------------------------------------------------------------------------
// Tensor-core GEMM via mma.sync + cp.async + ldmatrix.
// CTA 128x128, K-tile 32, 3-stage cp.async, 2 CTAs/SM.
// ---------------------------------------------------------------------------
#define TS 36
#define BUFW (128*TS*2)          // words per stage (A then B)
#define GEMM_SMEM (3*BUFW*4)     // 110592 B

template<int RESID, int ROUND>
__global__ void __launch_bounds__(256, 2) gemm_mma(
    const float* __restrict__ A, const float* __restrict__ Bw,
    const float* __restrict__ bias, const float* __restrict__ R,
    float* __restrict__ C, int M, int N, int K)
{
    extern __shared__ float sm[];
    const uint32_t sbase = smem_u32(sm);
    const int tid  = threadIdx.x;
    const int wid  = tid >> 5, lane = tid & 31;
    const int g    = lane >> 2, tg = lane & 3;
    const int wm   = (wid >> 2) << 6;
    const int wn   = (wid & 3) << 5;
    const int bm   = blockIdx.y << 7, bn = blockIdx.x << 7;
    const int r0   = tid >> 3, c0 = (tid & 7) << 2;
    const int ntk  = K >> 5;

    // ldmatrix per-lane byte offsets (within a stage buffer)
    const int lrA = lane & 15;                  // row-within-16
    const int lcA = (lane >> 4) << 2;           // col 0 or 4 (words)
    uint32_t aoff[2];
#pragma unroll
    for (int mh = 0; mh < 2; mh++)              // A 16-row tiles come in 4; offsets for mi via +16*TS
        aoff[mh] = (uint32_t)(((wm + (mh << 4) + lrA) * TS + lcA) << 2);
    const int lrB = ((lane >> 4) << 3) + (lane & 7);
    const int lcB = ((lane >> 3) & 1) << 2;
    uint32_t boff[2];
#pragma unroll
    for (int p = 0; p < 2; p++)
        boff[p] = (uint32_t)(((wn + (p << 4) + lrB) * TS + lcB) << 2);

    float acc[4][4][4];
#pragma unroll
    for (int mi = 0; mi < 4; mi++)
#pragma unroll
        for (int ni = 0; ni < 4; ni++)
#pragma unroll
            for (int i = 0; i < 4; i++) acc[mi][ni][i] = 0.f;

    auto cp_tile = [&](int kt, int buf) {
        const int kc = kt << 5;
        const uint32_t da = sbase + (uint32_t)((buf * BUFW + r0 * TS + c0) << 2);
        const uint32_t db = da + (uint32_t)((128 * TS) << 2);
#pragma unroll
        for (int i = 0; i < 4; i++) {
            cp16(da + (uint32_t)((i << 5) * TS << 2),
                 A  + (size_t)(bm + r0 + (i << 5)) * K + kc + c0);
            cp16(db + (uint32_t)((i << 5) * TS << 2),
                 Bw + (size_t)(bn + r0 + (i << 5)) * K + kc + c0);
        }
        asm volatile("cp.async.commit_group;" ::: "memory");
    };

    cp_tile(0, 0);
    if (ntk > 1) cp_tile(1, 1);

    int buf = 0;
    for (int kt = 0; kt < ntk; kt++) {
        if (kt < ntk - 1)
            asm volatile("cp.async.wait_group 1;" ::: "memory");
        else
            asm volatile("cp.async.wait_group 0;" ::: "memory");
        __syncthreads();

        if (kt + 2 < ntk) {
            int nb = buf + 2; if (nb >= 3) nb -= 3;
            cp_tile(kt + 2, nb);
        }

        const uint32_t Ab = sbase + (uint32_t)((buf * BUFW) << 2);
        const uint32_t Bb = Ab + (uint32_t)((128 * TS) << 2);
#pragma unroll
        for (int ks = 0; ks < 4; ks++) {
            const uint32_t kb = (uint32_t)(ks << 5);   // ko*4 bytes
            uint32_t af[4][4], bf[4][2];
#pragma unroll
            for (int mi = 0; mi < 4; mi++)
                ldsm4(af[mi], Ab + aoff[mi & 1]
                              + (uint32_t)((mi >> 1) * ((TS << 5) << 2)) + kb);
#pragma unroll
            for (int p = 0; p < 2; p++) {
                uint32_t t4[4];
                ldsm4(t4, Bb + boff[p] + kb);
                bf[2*p][0]   = t4[0]; bf[2*p][1]   = t4[1];
                bf[2*p+1][0] = t4[2]; bf[2*p+1][1] = t4[3];
            }
#pragma unroll
            for (int mi = 0; mi < 4; mi++)
#pragma unroll
                for (int ni = 0; ni < 4; ni++)
                    mma_16x8x8_tf32(acc[mi][ni], af[mi], bf[ni]);
        }
        if (++buf == 3) buf = 0;
    }

#pragma unroll
    for (int mi = 0; mi < 4; mi++) {
#pragma unroll
        for (int ni = 0; ni < 4; ni++) {
            const int row = bm + wm + (mi << 4) + g;
            const int col = bn + wn + (ni << 3) + (tg << 1);
            float2 bb = *(const float2*)(bias + col);
            float2 v0 = make_float2(acc[mi][ni][0] + bb.x, acc[mi][ni][1] + bb.y);
            float2 v1 = make_float2(acc[mi][ni][2] + bb.x, acc[mi][ni][3] + bb.y);
            if (RESID) {
                float2 ra = *(const float2*)(R + (size_t)row * N + col);
                float2 rb = *(const float2*)(R + (size_t)(row + 8) * N + col);
                v0.x += ra.x; v0.y += ra.y; v1.x += rb.x; v1.y += rb.y;
            }
            if (ROUND) {
                v0.x = rtf32(v0.x); v0.y = rtf32(v0.y);
                v1.x = rtf32(v1.x); v1.y = rtf32(v1.y);
            }
            *(float2*)(C + (size_t)row * N + col)       = v0;
            *(float2*)(C + (size_t)(row + 8) * N + col) = v1;
        }
    }
}

// ---------------------------------------------------------------------------
// Windowed attention on tensor cores + ldmatrix for Q/P/K fragments.
// ---------------------------------------------------------------------------
#define APAD 68
#define ATTN_SMEM (3*64*APAD*4)

__global__ void __launch_bounds__(128) attn_mma(const float* __restrict__ qkv,
                                                float* __restrict__ out)
{
    extern __shared__ float smf[];
    float* Qs = smf;                 // 64 x 68 (rows reused for P per-warp)
    float* Ks = smf +     64 * APAD;
    float* Vs = smf + 2 * 64 * APAD;
    const int tid  = threadIdx.x;
    const int wid  = tid >> 5, lane = tid & 31;
    const int g    = lane >> 2, tg = lane & 3;
    const int m0   = wid << 4;
    const size_t base = ((size_t)(blockIdx.z * L_ + blockIdx.x * W_)) * (3 * D_)
                        + blockIdx.y * HD_;

    const uint32_t Qb = smem_u32(Qs);
    const uint32_t Kb = smem_u32(Ks);

    // ldmatrix per-lane offsets
    const int lrA = lane & 15;
    const int lcA = (lane >> 4) << 2;
    const uint32_t qoff = (uint32_t)(((m0 + lrA) * APAD + lcA) << 2);
    const int lrB = ((lane >> 4) << 3) + (lane & 7);
    const int lcB = ((lane >> 3) & 1) << 2;
    uint32_t koff[4];
#pragma unroll
    for (int p = 0; p < 4; p++)
        koff[p] = (uint32_t)((((p << 4) + lrB) * APAD + lcB) << 2);

    for (int i = tid; i < 64 * 16; i += 128) {
        const int r = i >> 4, c = (i & 15) << 2;
        const float* p = qkv + base + (size_t)r * (3 * D_) + c;
        *(float4*)(Qs + r * APAD + c) = *(const float4*)(p);
        *(float4*)(Ks + r * APAD + c) = *(const float4*)(p + D_);
        *(float4*)(Vs + r * APAD + c) = *(const float4*)(p + 2 * D_);
    }
    __syncthreads();

    // S = Q K^T
    float s[8][4];
#pragma unroll
    for (int t = 0; t < 8; t++)
#pragma unroll
        for (int i = 0; i < 4; i++) s[t][i] = 0.f;

#pragma unroll
    for (int ks = 0; ks < 8; ks++) {
        const uint32_t kb = (uint32_t)(ks << 5);
        uint32_t a[4], bfr[8][2];
        ldsm4(a, Qb + qoff + kb);
#pragma unroll
        for (int p = 0; p < 4; p++) {
            uint32_t t4[4];
            ldsm4(t4, Kb + koff[p] + kb);
            bfr[2*p][0]   = t4[0]; bfr[2*p][1]   = t4[1];
            bfr[2*p+1][0] = t4[2]; bfr[2*p+1][1] = t4[3];
        }
#pragma unroll
        for (int t = 0; t < 8; t++)
            mma_16x8x8_tf32(s[t], a, bfr[t]);
    }

    // softmax over 64 cols; rows g (c0,c1) and g+8 (c2,c3)
    float mxl = -3.0e38f, mxh = -3.0e38f;
#pragma unroll
    for (int t = 0; t < 8; t++) {
#pragma unroll
        for (int i = 0; i < 4; i++) s[t][i] *= 0.125f;
        mxl = fmaxf(mxl, fmaxf(s[t][0], s[t][1]));
        mxh = fmaxf(mxh, fmaxf(s[t][2], s[t][3]));
    }
    mxl = fmaxf(mxl, __shfl_xor_sync(0xffffffffu, mxl, 1));
    mxl = fmaxf(mxl, __shfl_xor_sync(0xffffffffu, mxl, 2));
    mxh = fmaxf(mxh, __shfl_xor_sync(0xffffffffu, mxh, 1));
    mxh = fmaxf(mxh, __shfl_xor_sync(0xffffffffu, mxh, 2));

    float sl = 0.f, sh = 0.f;
#pragma unroll
    for (int t = 0; t < 8; t++) {
        s[t][0] = __expf(s[t][0] - mxl); sl += s[t][0];
        s[t][1] = __expf(s[t][1] - mxl); sl += s[t][1];
        s[t][2] = __expf(s[t][2] - mxh); sh += s[t][2];
        s[t][3] = __expf(s[t][3] - mxh); sh += s[t][3];
    }
    sl += __shfl_xor_sync(0xffffffffu, sl, 1);
    sl += __shfl_xor_sync(0xffffffffu, sl, 2);
    sh += __shfl_xor_sync(0xffffffffu, sh, 1);
    sh += __shfl_xor_sync(0xffffffffu, sh, 2);
    const float il = 1.0f / sl, ih = 1.0f / sh;

#pragma unroll
    for (int t = 0; t < 8; t++) {
        const int cc = (t << 3) + (tg << 1);
        *(float2*)(Qs + (m0 + g) * APAD + cc) =
            make_float2(rtf32(s[t][0] * il), rtf32(s[t][1] * il));
        *(float2*)(Qs + (m0 + g + 8) * APAD + cc) =
            make_float2(rtf32(s[t][2] * ih), rtf32(s[t][3] * ih));
    }
    __syncwarp();

    // O = P V
    float o[8][4];
#pragma unroll
    for (int t = 0; t < 8; t++)
#pragma unroll
        for (int i = 0; i < 4; i++) o[t][i] = 0.f;

#pragma unroll
    for (int ks = 0; ks < 8; ks++) {
        const int ko = ks << 3;
        uint32_t a[4];
        ldsm4(a, Qb + qoff + (uint32_t)(ko << 2));
#pragma unroll
        for (int t = 0; t < 8; t++) {
            uint32_t b[2];
            b[0] = __float_as_uint(Vs[(ko + tg) * APAD + (t << 3) + g]);
            b[1] = __float_as_uint(Vs[(ko + tg + 4) * APAD + (t << 3) + g]);
            mma_16x8x8_tf32(o[t], a, b);
        }
    }

    const size_t row = (size_t)(blockIdx.z * L_ + blockIdx.x * W_ + m0 + g);
    const int colb = blockIdx.y * HD_;
#pragma unroll
    for (int t = 0; t < 8; t++) {
        const int cc = colb + (t << 3) + (tg << 1);
        *(float2*)(out + row * D_ + cc) =
            make_float2(rtf32(o[t][0]), rtf32(o[t][1]));
        *(float2*)(out + (row + 8) * D_ + cc) =
            make_float2(rtf32(o[t][2]), rtf32(o[t][3]));
    }
}

// ---------------------------------------------------------------------------
// LayerNorm: one block per row of 1024.
// ---------------------------------------------------------------------------
__global__ void __launch_bounds__(256) ln_kernel(const float* __restrict__ y,
                                                 const float* __restrict__ gamma,
                                                 const float* __restrict__ beta,
                                                 float* __restrict__ out)
{
    __shared__ float red[8];
    const int row = blockIdx.x, tid = threadIdx.x;
    const float* yr = y + (size_t)row * D_;
    float4 v = *(const float4*)(yr + (tid << 2));

    float sAcc = v.x + v.y + v.z + v.w;
#pragma unroll
    for (int o = 16; o > 0; o >>= 1) sAcc += __shfl_xor_sync(0xffffffffu, sAcc, o);
    if ((tid & 31) == 0) red[tid >> 5] = sAcc;
    __syncthreads();
    float tot = 0.f;
#pragma unroll
    for (int i = 0; i < 8; i++) tot += red[i];
    const float mean = tot * (1.0f / 1024.0f);

    const float dx = v.x - mean, dy = v.y - mean, dz = v.z - mean, dw = v.w - mean;
    float s2 = dx * dx + dy * dy + dz * dz + dw * dw;
#pragma unroll
    for (int o = 16; o > 0; o >>= 1) s2 += __shfl_xor_sync(0xffffffffu, s2, o);
    __syncthreads();
    if ((tid & 31) == 0) red[tid >> 5] = s2;
    __syncthreads();
    float tot2 = 0.f;
#pragma unroll
    for (int i = 0; i < 8; i++) tot2 += red[i];
    const float rstd = rsqrtf(tot2 * (1.0f / 1024.0f) + EPS_);

    float4 gm = *(const float4*)(gamma + (tid << 2));
    float4 be = *(const float4*)(beta  + (tid << 2));
    float4 o4 = make_float4(dx * rstd * gm.x + be.x,
                            dy * rstd * gm.y + be.y,
                            dz * rstd * gm.z + be.z,
                            dw * rstd * gm.w + be.w);
    *(float4*)(out + (size_t)row * D_ + (tid << 2)) = o4;
}

// ---------------------------------------------------------------------------
extern "C" void kernel_launch(void* const* d_in, const int* in_sizes, int n_in,
                              void* d_out, int out_size)
{
    const float* x     = (const float*)d_in[0];
    const float* Wqkv  = (const float*)d_in[1];
    const float* bqkv  = (const float*)d_in[2];
    const float* Wproj = (const float*)d_in[3];
    const float* bproj = (const float*)d_in[4];
    const float* gamma = (const float*)d_in[5];
    const float* beta  = (const float*)d_in[6];
    float* out = (float*)d_out;

    float *qkv, *attn, *y, *xr, *wq, *wp;
    cudaGetSymbolAddress((void**)&qkv,  g_qkv);
    cudaGetSymbolAddress((void**)&attn, g_attn);
    cudaGetSymbolAddress((void**)&y,    g_y);
    cudaGetSymbolAddress((void**)&xr,   g_xr);
    cudaGetSymbolAddress((void**)&wq,   g_wq);
    cudaGetSymbolAddress((void**)&wp,   g_wp);

    cudaFuncSetAttribute(gemm_mma<0,1>, cudaFuncAttributeMaxDynamicSharedMemorySize, GEMM_SMEM);
    cudaFuncSetAttribute(gemm_mma<1,0>, cudaFuncAttributeMaxDynamicSharedMemorySize, GEMM_SMEM);
    cudaFuncSetAttribute(attn_mma, cudaFuncAttributeMaxDynamicSharedMemorySize, ATTN_SMEM);

    // 0) round GEMM operands to tf32 once
    round_tf32<<<(ML_*D_/4 + 255)/256, 256>>>(x,     xr, ML_*D_/4);
    round_tf32<<<(3*D_*D_/4 + 255)/256, 256>>>(Wqkv, wq, 3*D_*D_/4);
    round_tf32<<<(D_*D_/4 + 255)/256, 256>>>(Wproj,  wp, D_*D_/4);

    // 1) QKV projection (epilogue rounds Q,K,V for the attention MMA)
    gemm_mma<0,1><<<dim3(24, 128), 256, GEMM_SMEM>>>(xr, wq, bqkv, xr, qkv,
                                                     ML_, 3 * D_, D_);
    // 2) windowed attention on tensor cores
    attn_mma<<<dim3(64, 16, 4), 128, ATTN_SMEM>>>(qkv, attn);
    // 3) output projection + bias + residual (residual = original x)
    gemm_mma<1,0><<<dim3(8, 128), 256, GEMM_SMEM>>>(attn, wp, bproj, x, y,
                                                    ML_, D_, D_);
    // 4) layernorm
    ln_kernel<<<ML_, 256>>>(y, gamma, beta, out);
}

// round 8
// speedup vs baseline: 4.6842x; 1.0405x over previous
#include <cuda_runtime.h>
#include <cstdint>

#define B_ 4
#define L_ 4096
#define D_ 1024
#define H_ 16
#define W_ 64
#define HD_ 64
#define ML_ (B_*L_)      // 16384 rows
#define EPS_ 1e-5f

// Scratch (allocation-free rule: __device__ globals)
__device__ float g_qkv [(size_t)ML_ * 3 * D_];   // [B*L, 3*D] (tf32-rounded)
__device__ float g_attn[(size_t)ML_ * D_];       // [B*L, D]   (tf32-rounded)
__device__ float g_y   [(size_t)ML_ * D_];       // pre-LN residual sum
__device__ float g_xr  [(size_t)ML_ * D_];       // x rounded to tf32
__device__ float g_wq  [(size_t)3 * D_ * D_];    // Wqkv rounded
__device__ float g_wp  [(size_t)D_ * D_];        // Wproj rounded

// ---------------------------------------------------------------------------
__device__ __forceinline__ uint32_t f2tf32(float f) {
    uint32_t u;
    asm("cvt.rna.tf32.f32 %0, %1;" : "=r"(u) : "f"(f));
    return u;
}
__device__ __forceinline__ float rtf32(float f) {
    return __uint_as_float(f2tf32(f));
}
__device__ __forceinline__ uint32_t smem_u32(const void* p) {
    uint32_t a;
    asm("{ .reg .u64 t; cvta.to.shared.u64 t, %1; cvt.u32.u64 %0, t; }"
        : "=r"(a) : "l"(p));
    return a;
}
__device__ __forceinline__ void cp16(uint32_t dst, const void* src) {
    asm volatile("cp.async.cg.shared.global [%0], [%1], 16;"
                 :: "r"(dst), "l"(src) : "memory");
}
__device__ __forceinline__ void mma_16x8x8_tf32(float* c, const uint32_t* a,
                                                const uint32_t* b) {
    asm volatile(
        "mma.sync.aligned.m16n8k8.row.col.f32.tf32.tf32.f32 "
        "{%0,%1,%2,%3}, {%4,%5,%6,%7}, {%8,%9}, {%0,%1,%2,%3};"
        : "+f"(c[0]), "+f"(c[1]), "+f"(c[2]), "+f"(c[3])
        : "r"(a[0]), "r"(a[1]), "r"(a[2]), "r"(a[3]), "r"(b[0]), "r"(b[1]));
}
// ldmatrix x4 b16: viewed as b32, r_i[lane l] = tile_i[l>>2][l&3] where
// tile_i is addressed by lanes 8i..8i+7 (lane j -> row j of the 8x(16B) tile).
__device__ __forceinline__ void ldsm4(uint32_t* r, uint32_t addr) {
    asm volatile("ldmatrix.sync.aligned.m8n8.x4.shared.b16 {%0,%1,%2,%3}, [%4];"
                 : "=r"(r[0]), "=r"(r[1]), "=r"(r[2]), "=r"(r[3]) : "r"(addr));
}

// ---------------------------------------------------------------------------
// Elementwise tf32 rounding prepass
// ---------------------------------------------------------------------------
__global__ void round_tf32(const float* __restrict__ in, float* __restrict__ out,
                           int n4)
{
    int i = blockIdx.x * blockDim.x + threadIdx.x;
    if (i < n4) {
        float4 v = ((const float4*)in)[i];
        v.x = rtf32(v.x); v.y = rtf32(v.y); v.z = rtf32(v.z); v.w = rtf32(v.w);
        ((float4*)out)[i] = v;
    }
}

// ---------------------------------------------------------------------------
// Tensor-core GEMM via mma.sync + cp.async + ldmatrix.
// CTA 128x128, K-tile 32, 3-stage cp.async, 2 CTAs/SM, A-fragment pipeline.
// ---------------------------------------------------------------------------
#define TS 36
#define BUFW (128*TS*2)          // words per stage (A then B)
#define GEMM_SMEM (3*BUFW*4)     // 110592 B

template<int RESID, int ROUND>
__global__ void __launch_bounds__(256, 2) gemm_mma(
    const float* __restrict__ A, const float* __restrict__ Bw,
    const float* __restrict__ bias, const float* __restrict__ R,
    float* __restrict__ C, int M, int N, int K)
{
    extern __shared__ float sm[];
    const uint32_t sbase = smem_u32(sm);
    const int tid  = threadIdx.x;
    const int wid  = tid >> 5, lane = tid & 31;
    const int g    = lane >> 2, tg = lane & 3;
    const int wm   = (wid >> 2) << 6;
    const int wn   = (wid & 3) << 5;
    const int bm   = blockIdx.y << 7, bn = blockIdx.x << 7;
    const int r0   = tid >> 3, c0 = (tid & 7) << 2;
    const int ntk  = K >> 5;

    // ldmatrix per-lane byte offsets (within a stage buffer)
    const int lrA = lane & 15;                  // row-within-16
    const int lcA = (lane >> 4) << 2;           // col 0 or 4 (words)
    uint32_t aoff[2];
#pragma unroll
    for (int mh = 0; mh < 2; mh++)
        aoff[mh] = (uint32_t)(((wm + (mh << 4) + lrA) * TS + lcA) << 2);
    const int lrB = ((lane >> 4) << 3) + (lane & 7);
    const int lcB = ((lane >> 3) & 1) << 2;
    uint32_t boff[2];
#pragma unroll
    for (int p = 0; p < 2; p++)
        boff[p] = (uint32_t)(((wn + (p << 4) + lrB) * TS + lcB) << 2);

    float acc[4][4][4];
#pragma unroll
    for (int mi = 0; mi < 4; mi++)
#pragma unroll
        for (int ni = 0; ni < 4; ni++)
#pragma unroll
            for (int i = 0; i < 4; i++) acc[mi][ni][i] = 0.f;

    auto cp_tile = [&](int kt, int buf) {
        const int kc = kt << 5;
        const uint32_t da = sbase + (uint32_t)((buf * BUFW + r0 * TS + c0) << 2);
        const uint32_t db = da + (uint32_t)((128 * TS) << 2);
#pragma unroll
        for (int i = 0; i < 4; i++) {
            cp16(da + (uint32_t)((i << 5) * TS << 2),
                 A  + (size_t)(bm + r0 + (i << 5)) * K + kc + c0);
            cp16(db + (uint32_t)((i << 5) * TS << 2),
                 Bw + (size_t)(bn + r0 + (i << 5)) * K + kc + c0);
        }
        asm volatile("cp.async.commit_group;" ::: "memory");
    };

    cp_tile(0, 0);
    if (ntk > 1) cp_tile(1, 1);

    int buf = 0;
    for (int kt = 0; kt < ntk; kt++) {
        if (kt < ntk - 1)
            asm volatile("cp.async.wait_group 1;" ::: "memory");
        else
            asm volatile("cp.async.wait_group 0;" ::: "memory");
        __syncthreads();

        const uint32_t Ab = sbase + (uint32_t)((buf * BUFW) << 2);
        const uint32_t Bb = Ab + (uint32_t)((128 * TS) << 2);

        // A-fragment software pipeline: load ks=0, then prefetch ks+1
        uint32_t afb[2][4][4];
#pragma unroll
        for (int mi = 0; mi < 4; mi++)
            ldsm4(afb[0][mi], Ab + aoff[mi & 1]
                          + (uint32_t)((mi >> 1) * ((TS << 5) << 2)));

#pragma unroll
        for (int ks = 0; ks < 4; ks++) {
            const uint32_t kb = (uint32_t)(ks << 5);   // ko*4 bytes
            uint32_t bf[4][2];
#pragma unroll
            for (int p = 0; p < 2; p++) {
                uint32_t t4[4];
                ldsm4(t4, Bb + boff[p] + kb);
                bf[2*p][0]   = t4[0]; bf[2*p][1]   = t4[1];
                bf[2*p+1][0] = t4[2]; bf[2*p+1][1] = t4[3];
            }
            if (ks < 3) {
                const uint32_t kb2 = (uint32_t)((ks + 1) << 5);
#pragma unroll
                for (int mi = 0; mi < 4; mi++)
                    ldsm4(afb[(ks + 1) & 1][mi], Ab + aoff[mi & 1]
                                  + (uint32_t)((mi >> 1) * ((TS << 5) << 2)) + kb2);
            }
#pragma unroll
            for (int ni = 0; ni < 4; ni++)
#pragma unroll
                for (int mi = 0; mi < 4; mi++)
                    mma_16x8x8_tf32(acc[mi][ni], afb[ks & 1][mi], bf[ni]);

            // issue next-stage cp.async after first MMA batch (tensor pipe hot)
            if (ks == 0 && kt + 2 < ntk) {
                int nb = buf + 2; if (nb >= 3) nb -= 3;
                cp_tile(kt + 2, nb);
            }
        }
        if (++buf == 3) buf = 0;
    }

#pragma unroll
    for (int mi = 0; mi < 4; mi++) {
#pragma unroll
        for (int ni = 0; ni < 4; ni++) {
            const int row = bm + wm + (mi << 4) + g;
            const int col = bn + wn + (ni << 3) + (tg << 1);
            float2 bb = *(const float2*)(bias + col);
            float2 v0 = make_float2(acc[mi][ni][0] + bb.x, acc[mi][ni][1] + bb.y);
            float2 v1 = make_float2(acc[mi][ni][2] + bb.x, acc[mi][ni][3] + bb.y);
            if (RESID) {
                float2 ra = *(const float2*)(R + (size_t)row * N + col);
                float2 rb = *(const float2*)(R + (size_t)(row + 8) * N + col);
                v0.x += ra.x; v0.y += ra.y; v1.x += rb.x; v1.y += rb.y;
            }
            if (ROUND) {
                v0.x = rtf32(v0.x); v0.y = rtf32(v0.y);
                v1.x = rtf32(v1.x); v1.y = rtf32(v1.y);
            }
            *(float2*)(C + (size_t)row * N + col)       = v0;
            *(float2*)(C + (size_t)(row + 8) * N + col) = v1;
        }
    }
}

// ---------------------------------------------------------------------------
// Windowed attention on tensor cores + ldmatrix for Q/P/K fragments.
// ---------------------------------------------------------------------------
#define APAD 68
#define ATTN_SMEM (3*64*APAD*4)

__global__ void __launch_bounds__(128) attn_mma(const float* __restrict__ qkv,
                                                float* __restrict__ out)
{
    extern __shared__ float smf[];
    float* Qs = smf;                 // 64 x 68 (rows reused for P per-warp)
    float* Ks = smf +     64 * APAD;
    float* Vs = smf + 2 * 64 * APAD;
    const int tid  = threadIdx.x;
    const int wid  = tid >> 5, lane = tid & 31;
    const int g    = lane >> 2, tg = lane & 3;
    const int m0   = wid << 4;
    const size_t base = ((size_t)(blockIdx.z * L_ + blockIdx.x * W_)) * (3 * D_)
                        + blockIdx.y * HD_;

    const uint32_t Qb = smem_u32(Qs);
    const uint32_t Kb = smem_u32(Ks);

    // ldmatrix per-lane offsets
    const int lrA = lane & 15;
    const int lcA = (lane >> 4) << 2;
    const uint32_t qoff = (uint32_t)(((m0 + lrA) * APAD + lcA) << 2);
    const int lrB = ((lane >> 4) << 3) + (lane & 7);
    const int lcB = ((lane >> 3) & 1) << 2;
    uint32_t koff[4];
#pragma unroll
    for (int p = 0; p < 4; p++)
        koff[p] = (uint32_t)((((p << 4) + lrB) * APAD + lcB) << 2);

    for (int i = tid; i < 64 * 16; i += 128) {
        const int r = i >> 4, c = (i & 15) << 2;
        const float* p = qkv + base + (size_t)r * (3 * D_) + c;
        *(float4*)(Qs + r * APAD + c) = *(const float4*)(p);
        *(float4*)(Ks + r * APAD + c) = *(const float4*)(p + D_);
        *(float4*)(Vs + r * APAD + c) = *(const float4*)(p + 2 * D_);
    }
    __syncthreads();

    // S = Q K^T
    float s[8][4];
#pragma unroll
    for (int t = 0; t < 8; t++)
#pragma unroll
        for (int i = 0; i < 4; i++) s[t][i] = 0.f;

#pragma unroll
    for (int ks = 0; ks < 8; ks++) {
        const uint32_t kb = (uint32_t)(ks << 5);
        uint32_t a[4], bfr[8][2];
        ldsm4(a, Qb + qoff + kb);
#pragma unroll
        for (int p = 0; p < 4; p++) {
            uint32_t t4[4];
            ldsm4(t4, Kb + koff[p] + kb);
            bfr[2*p][0]   = t4[0]; bfr[2*p][1]   = t4[1];
            bfr[2*p+1][0] = t4[2]; bfr[2*p+1][1] = t4[3];
        }
#pragma unroll
        for (int t = 0; t < 8; t++)
            mma_16x8x8_tf32(s[t], a, bfr[t]);
    }

    // softmax over 64 cols; rows g (c0,c1) and g+8 (c2,c3)
    float mxl = -3.0e38f, mxh = -3.0e38f;
#pragma unroll
    for (int t = 0; t < 8; t++) {
#pragma unroll
        for (int i = 0; i < 4; i++) s[t][i] *= 0.125f;
        mxl = fmaxf(mxl, fmaxf(s[t][0], s[t][1]));
        mxh = fmaxf(mxh, fmaxf(s[t][2], s[t][3]));
    }
    mxl = fmaxf(mxl, __shfl_xor_sync(0xffffffffu, mxl, 1));
    mxl = fmaxf(mxl, __shfl_xor_sync(0xffffffffu, mxl, 2));
    mxh = fmaxf(mxh, __shfl_xor_sync(0xffffffffu, mxh, 1));
    mxh = fmaxf(mxh, __shfl_xor_sync(0xffffffffu, mxh, 2));

    float sl = 0.f, sh = 0.f;
#pragma unroll
    for (int t = 0; t < 8; t++) {
        s[t][0] = __expf(s[t][0] - mxl); sl += s[t][0];
        s[t][1] = __expf(s[t][1] - mxl); sl += s[t][1];
        s[t][2] = __expf(s[t][2] - mxh); sh += s[t][2];
        s[t][3] = __expf(s[t][3] - mxh); sh += s[t][3];
    }
    sl += __shfl_xor_sync(0xffffffffu, sl, 1);
    sl += __shfl_xor_sync(0xffffffffu, sl, 2);
    sh += __shfl_xor_sync(0xffffffffu, sh, 1);
    sh += __shfl_xor_sync(0xffffffffu, sh, 2);
    const float il = 1.0f / sl, ih = 1.0f / sh;

#pragma unroll
    for (int t = 0; t < 8; t++) {
        const int cc = (t << 3) + (tg << 1);
        *(float2*)(Qs + (m0 + g) * APAD + cc) =
            make_float2(rtf32(s[t][0] * il), rtf32(s[t][1] * il));
        *(float2*)(Qs + (m0 + g + 8) * APAD + cc) =
            make_float2(rtf32(s[t][2] * ih), rtf32(s[t][3] * ih));
    }
    __syncwarp();

    // O = P V
    float o[8][4];
#pragma unroll
    for (int t = 0; t < 8; t++)
#pragma unroll
        for (int i = 0; i < 4; i++) o[t][i] = 0.f;

#pragma unroll
    for (int ks = 0; ks < 8; ks++) {
        const int ko = ks << 3;
        uint32_t a[4];
        ldsm4(a, Qb + qoff + (uint32_t)(ko << 2));
#pragma unroll
        for (int t = 0; t < 8; t++) {
            uint32_t b[2];
            b[0] = __float_as_uint(Vs[(ko + tg) * APAD + (t << 3) + g]);
            b[1] = __float_as_uint(Vs[(ko + tg + 4) * APAD + (t << 3) + g]);
            mma_16x8x8_tf32(o[t], a, b);
        }
    }

    const size_t row = (size_t)(blockIdx.z * L_ + blockIdx.x * W_ + m0 + g);
    const int colb = blockIdx.y * HD_;
#pragma unroll
    for (int t = 0; t < 8; t++) {
        const int cc = colb + (t << 3) + (tg << 1);
        *(float2*)(out + row * D_ + cc) =
            make_float2(rtf32(o[t][0]), rtf32(o[t][1]));
        *(float2*)(out + (row + 8) * D_ + cc) =
            make_float2(rtf32(o[t][2]), rtf32(o[t][3]));
    }
}

// ---------------------------------------------------------------------------
// LayerNorm: one block per row of 1024.
// ---------------------------------------------------------------------------
__global__ void __launch_bounds__(256) ln_kernel(const float* __restrict__ y,
                                                 const float* __restrict__ gamma,
                                                 const float* __restrict__ beta,
                                                 float* __restrict__ out)
{
    __shared__ float red[8];
    const int row = blockIdx.x, tid = threadIdx.x;
    const float* yr = y + (size_t)row * D_;
    float4 v = *(const float4*)(yr + (tid << 2));

    float sAcc = v.x + v.y + v.z + v.w;
#pragma unroll
    for (int o = 16; o > 0; o >>= 1) sAcc += __shfl_xor_sync(0xffffffffu, sAcc, o);
    if ((tid & 31) == 0) red[tid >> 5] = sAcc;
    __syncthreads();
    float tot = 0.f;
#pragma unroll
    for (int i = 0; i < 8; i++) tot += red[i];
    const float mean = tot * (1.0f / 1024.0f);

    const float dx = v.x - mean, dy = v.y - mean, dz = v.z - mean, dw = v.w - mean;
    float s2 = dx * dx + dy * dy + dz * dz + dw * dw;
#pragma unroll
    for (int o = 16; o > 0; o >>= 1) s2 += __shfl_xor_sync(0xffffffffu, s2, o);
    __syncthreads();
    if ((tid & 31) == 0) red[tid >> 5] = s2;
    __syncthreads();
    float tot2 = 0.f;
#pragma unroll
    for (int i = 0; i < 8; i++) tot2 += red[i];
    const float rstd = rsqrtf(tot2 * (1.0f / 1024.0f) + EPS_);

    float4 gm = *(const float4*)(gamma + (tid << 2));
    float4 be = *(const float4*)(beta  + (tid << 2));
    float4 o4 = make_float4(dx * rstd * gm.x + be.x,
                            dy * rstd * gm.y + be.y,
                            dz * rstd * gm.z + be.z,
                            dw * rstd * gm.w + be.w);
    *(float4*)(out + (size_t)row * D_ + (tid << 2)) = o4;
}

// ---------------------------------------------------------------------------
extern "C" void kernel_launch(void* const* d_in, const int* in_sizes, int n_in,
                              void* d_out, int out_size)
{
    const float* x     = (const float*)d_in[0];
    const float* Wqkv  = (const float*)d_in[1];
    const float* bqkv  = (const float*)d_in[2];
    const float* Wproj = (const float*)d_in[3];
    const float* bproj = (const float*)d_in[4];
    const float* gamma = (const float*)d_in[5];
    const float* beta  = (const float*)d_in[6];
    float* out = (float*)d_out;

    float *qkv, *attn, *y, *xr, *wq, *wp;
    cudaGetSymbolAddress((void**)&qkv,  g_qkv);
    cudaGetSymbolAddress((void**)&attn, g_attn);
    cudaGetSymbolAddress((void**)&y,    g_y);
    cudaGetSymbolAddress((void**)&xr,   g_xr);
    cudaGetSymbolAddress((void**)&wq,   g_wq);
    cudaGetSymbolAddress((void**)&wp,   g_wp);

    cudaFuncSetAttribute(gemm_mma<0,1>, cudaFuncAttributeMaxDynamicSharedMemorySize, GEMM_SMEM);
    cudaFuncSetAttribute(gemm_mma<1,0>, cudaFuncAttributeMaxDynamicSharedMemorySize, GEMM_SMEM);
    cudaFuncSetAttribute(attn_mma, cudaFuncAttributeMaxDynamicSharedMemorySize, ATTN_SMEM);

    // 0) round GEMM operands to tf32 once
    round_tf32<<<(ML_*D_/4 + 255)/256, 256>>>(x,     xr, ML_*D_/4);
    round_tf32<<<(3*D_*D_/4 + 255)/256, 256>>>(Wqkv, wq, 3*D_*D_/4);
    round_tf32<<<(D_*D_/4 + 255)/256, 256>>>(Wproj,  wp, D_*D_/4);

    // 1) QKV projection (epilogue rounds Q,K,V for the attention MMA)
    gemm_mma<0,1><<<dim3(24, 128), 256, GEMM_SMEM>>>(xr, wq, bqkv, xr, qkv,
                                                     ML_, 3 * D_, D_);
    // 2) windowed attention on tensor cores
    attn_mma<<<dim3(64, 16, 4), 128, ATTN_SMEM>>>(qkv, attn);
    // 3) output projection + bias + residual (residual = original x)
    gemm_mma<1,0><<<dim3(8, 128), 256, GEMM_SMEM>>>(attn, wp, bproj, x, y,
                                                    ML_, D_, D_);
    // 4) layernorm
    ln_kernel<<<ML_, 256>>>(y, gamma, beta, out);
}